// round 1
// baseline (speedup 1.0000x reference)
#include <cuda_runtime.h>
#include <math.h>

// Problem constants
#define T_TOK 4096      // B*L tokens
#define Dd    1024      // model dim
#define Hh    512       // expert hidden
#define Ee    16        // num experts
#define Ss    2048      // shared expert hidden
#define TOPK  2

// ---------------- device scratch (no allocations allowed) ----------------
__device__ float g_buf[T_TOK * Ss];               // 32 MB: silu(x@sfc1)* (x@sfc2)
__device__ float h_buf[T_TOK * TOPK * Hh];        // 16 MB: per-sorted-position expert hidden
__device__ float slot_out[T_TOK * TOPK * Dd];     // 32 MB: per-slot expert output (weighted)
__device__ int   d_top_idx[T_TOK * TOPK];
__device__ float d_top_w[T_TOK * TOPK];
__device__ int   d_counts[Ee];
__device__ int   d_offsets[Ee + 1];
__device__ int   d_cursor[Ee];
__device__ int   d_perm[T_TOK * TOPK];            // sorted-by-expert slot ids (slot = t*2+k)

__device__ __forceinline__ float silu_f(float v) { return v / (1.0f + expf(-v)); }

// ---------------- routing ----------------
__global__ void zero_counts_kernel() {
    if (threadIdx.x < Ee) d_counts[threadIdx.x] = 0;
}

// one warp per token: 16 dot products of length 1024, top-2, softmax over selected
__global__ void router_kernel(const float* __restrict__ x, const float* __restrict__ gw) {
    int warp = threadIdx.x >> 5;
    int lane = threadIdx.x & 31;
    int t = blockIdx.x * 4 + warp;
    if (t >= T_TOK) return;
    const float* xr = x + (size_t)t * Dd;
    float logits[Ee];
    #pragma unroll 1
    for (int e = 0; e < Ee; e++) {
        const float* w = gw + (size_t)e * Dd;
        float p = 0.0f;
        for (int d = lane; d < Dd; d += 32) p += xr[d] * w[d];
        #pragma unroll
        for (int o = 16; o; o >>= 1) p += __shfl_down_sync(0xffffffffu, p, o);
        if (lane == 0) logits[e] = p;
    }
    if (lane == 0) {
        int i0 = 0; float v0 = logits[0];
        #pragma unroll
        for (int e = 1; e < Ee; e++) if (logits[e] > v0) { v0 = logits[e]; i0 = e; }
        int i1 = -1; float v1 = -3.0e38f;
        #pragma unroll
        for (int e = 0; e < Ee; e++) if (e != i0 && logits[e] > v1) { v1 = logits[e]; i1 = e; }
        float ex = expf(v1 - v0);               // <= 1
        float w0 = 1.0f / (1.0f + ex);
        float w1 = ex / (1.0f + ex);
        d_top_idx[2 * t]     = i0;
        d_top_idx[2 * t + 1] = i1;
        d_top_w[2 * t]       = w0;
        d_top_w[2 * t + 1]   = w1;
        atomicAdd(&d_counts[i0], 1);
        atomicAdd(&d_counts[i1], 1);
    }
}

__global__ void scan_kernel() {
    int o = 0;
    for (int e = 0; e < Ee; e++) { d_offsets[e] = o; d_cursor[e] = o; o += d_counts[e]; }
    d_offsets[Ee] = o;
}

__global__ void scatter_kernel() {
    int s = blockIdx.x * blockDim.x + threadIdx.x;
    if (s < T_TOK * TOPK) {
        int e = d_top_idx[s];
        int p = atomicAdd(&d_cursor[e], 1);
        d_perm[p] = s;
    }
}

// ---------------- GEMM tiles: 64x64x16, 256 threads, 4x4 per thread ----------------
// All operands K-major (row-contiguous in K), "NT" style.

// shared expert GEMM1 (fused dual-B): g = silu(x@sfc1^T) * (x@sfc2^T)   [T x S], K=D
__global__ void __launch_bounds__(256) shared_gemm1_kernel(
    const float* __restrict__ x, const float* __restrict__ s1w, const float* __restrict__ s2w)
{
    __shared__ float As[16][68], B1s[16][68], B2s[16][68];
    int tid = threadIdx.x;
    int tx = tid & 15, ty = tid >> 4;
    int row0 = blockIdx.y * 64, col0 = blockIdx.x * 64;
    int lr = tid >> 2, lv = tid & 3;
    const float4* Ap  = (const float4*)(x   + (size_t)(row0 + lr) * Dd) + lv;
    const float4* B1p = (const float4*)(s1w + (size_t)(col0 + lr) * Dd) + lv;
    const float4* B2p = (const float4*)(s2w + (size_t)(col0 + lr) * Dd) + lv;
    float acc1[4][4], acc2[4][4];
    #pragma unroll
    for (int i = 0; i < 4; i++)
        #pragma unroll
        for (int j = 0; j < 4; j++) { acc1[i][j] = 0.f; acc2[i][j] = 0.f; }

    for (int k0 = 0; k0 < Dd / 4; k0 += 4) {
        float4 a = Ap[k0], b1 = B1p[k0], b2 = B2p[k0];
        __syncthreads();
        As[lv*4+0][lr] = a.x;  As[lv*4+1][lr] = a.y;  As[lv*4+2][lr] = a.z;  As[lv*4+3][lr] = a.w;
        B1s[lv*4+0][lr] = b1.x; B1s[lv*4+1][lr] = b1.y; B1s[lv*4+2][lr] = b1.z; B1s[lv*4+3][lr] = b1.w;
        B2s[lv*4+0][lr] = b2.x; B2s[lv*4+1][lr] = b2.y; B2s[lv*4+2][lr] = b2.z; B2s[lv*4+3][lr] = b2.w;
        __syncthreads();
        #pragma unroll
        for (int k = 0; k < 16; k++) {
            float4 av  = *(const float4*)&As[k][ty * 4];
            float4 bv1 = *(const float4*)&B1s[k][tx * 4];
            float4 bv2 = *(const float4*)&B2s[k][tx * 4];
            float ar[4]  = {av.x, av.y, av.z, av.w};
            float br1[4] = {bv1.x, bv1.y, bv1.z, bv1.w};
            float br2[4] = {bv2.x, bv2.y, bv2.z, bv2.w};
            #pragma unroll
            for (int i = 0; i < 4; i++)
                #pragma unroll
                for (int j = 0; j < 4; j++) {
                    acc1[i][j] += ar[i] * br1[j];
                    acc2[i][j] += ar[i] * br2[j];
                }
        }
    }
    #pragma unroll
    for (int i = 0; i < 4; i++) {
        int r = row0 + ty * 4 + i;
        #pragma unroll
        for (int j = 0; j < 4; j++) {
            int c = col0 + tx * 4 + j;
            g_buf[(size_t)r * Ss + c] = silu_f(acc1[i][j]) * acc2[i][j];
        }
    }
}

// shared expert GEMM2: out(shared part) = g @ sfc3^T   [T x D], K=S
__global__ void __launch_bounds__(256) shared_gemm2_kernel(
    const float* __restrict__ s3w, float* __restrict__ out)
{
    __shared__ float As[16][68], Bs[16][68];
    int tid = threadIdx.x;
    int tx = tid & 15, ty = tid >> 4;
    int row0 = blockIdx.y * 64, col0 = blockIdx.x * 64;
    int lr = tid >> 2, lv = tid & 3;
    const float4* Ap = (const float4*)(g_buf + (size_t)(row0 + lr) * Ss) + lv;
    const float4* Bp = (const float4*)(s3w  + (size_t)(col0 + lr) * Ss) + lv;
    float acc[4][4];
    #pragma unroll
    for (int i = 0; i < 4; i++)
        #pragma unroll
        for (int j = 0; j < 4; j++) acc[i][j] = 0.f;

    for (int k0 = 0; k0 < Ss / 4; k0 += 4) {
        float4 a = Ap[k0], b = Bp[k0];
        __syncthreads();
        As[lv*4+0][lr] = a.x; As[lv*4+1][lr] = a.y; As[lv*4+2][lr] = a.z; As[lv*4+3][lr] = a.w;
        Bs[lv*4+0][lr] = b.x; Bs[lv*4+1][lr] = b.y; Bs[lv*4+2][lr] = b.z; Bs[lv*4+3][lr] = b.w;
        __syncthreads();
        #pragma unroll
        for (int k = 0; k < 16; k++) {
            float4 av = *(const float4*)&As[k][ty * 4];
            float4 bv = *(const float4*)&Bs[k][tx * 4];
            float ar[4] = {av.x, av.y, av.z, av.w};
            float br[4] = {bv.x, bv.y, bv.z, bv.w};
            #pragma unroll
            for (int i = 0; i < 4; i++)
                #pragma unroll
                for (int j = 0; j < 4; j++) acc[i][j] += ar[i] * br[j];
        }
    }
    #pragma unroll
    for (int i = 0; i < 4; i++) {
        int r = row0 + ty * 4 + i;
        #pragma unroll
        for (int j = 0; j < 4; j++) {
            int c = col0 + tx * 4 + j;
            out[(size_t)r * Dd + c] = acc[i][j];
        }
    }
}

// MoE GEMM1 (gathered rows): h = silu(X_e @ w1[e]^T)   [M_e x H], K=D
// grid: (H/64, maxMtiles=128, E)
__global__ void __launch_bounds__(256) moe_gemm1_kernel(
    const float* __restrict__ x, const float* __restrict__ w1)
{
    int e = blockIdx.z;
    int Ms = d_offsets[e], Me = d_offsets[e + 1];
    int M = Me - Ms;
    int m0 = blockIdx.y * 64;
    if (m0 >= M) return;
    __shared__ float As[16][68], Bs[16][68];
    int tid = threadIdx.x;
    int tx = tid & 15, ty = tid >> 4;
    int col0 = blockIdx.x * 64;
    int lr = tid >> 2, lv = tid & 3;
    int mrow = m0 + lr;
    const float* arow = x;   // safe dummy for out-of-range rows (never stored)
    if (mrow < M) {
        int slot = d_perm[Ms + mrow];
        arow = x + (size_t)(slot >> 1) * Dd;
    }
    const float4* Ap = (const float4*)arow + lv;
    const float4* Bp = (const float4*)(w1 + (size_t)e * Hh * Dd + (size_t)(col0 + lr) * Dd) + lv;
    float acc[4][4];
    #pragma unroll
    for (int i = 0; i < 4; i++)
        #pragma unroll
        for (int j = 0; j < 4; j++) acc[i][j] = 0.f;

    for (int k0 = 0; k0 < Dd / 4; k0 += 4) {
        float4 a = Ap[k0], b = Bp[k0];
        __syncthreads();
        As[lv*4+0][lr] = a.x; As[lv*4+1][lr] = a.y; As[lv*4+2][lr] = a.z; As[lv*4+3][lr] = a.w;
        Bs[lv*4+0][lr] = b.x; Bs[lv*4+1][lr] = b.y; Bs[lv*4+2][lr] = b.z; Bs[lv*4+3][lr] = b.w;
        __syncthreads();
        #pragma unroll
        for (int k = 0; k < 16; k++) {
            float4 av = *(const float4*)&As[k][ty * 4];
            float4 bv = *(const float4*)&Bs[k][tx * 4];
            float ar[4] = {av.x, av.y, av.z, av.w};
            float br[4] = {bv.x, bv.y, bv.z, bv.w};
            #pragma unroll
            for (int i = 0; i < 4; i++)
                #pragma unroll
                for (int j = 0; j < 4; j++) acc[i][j] += ar[i] * br[j];
        }
    }
    #pragma unroll
    for (int i = 0; i < 4; i++) {
        int m = m0 + ty * 4 + i;
        if (m < M) {
            int p = Ms + m;
            #pragma unroll
            for (int j = 0; j < 4; j++) {
                int c = col0 + tx * 4 + j;
                h_buf[(size_t)p * Hh + c] = silu_f(acc[i][j]);
            }
        }
    }
}

// MoE GEMM2: slot_out[slot] = wk * (h_p @ w2[e]^T)   [M_e x D], K=H
// grid: (D/64, maxMtiles=128, E)
__global__ void __launch_bounds__(256) moe_gemm2_kernel(const float* __restrict__ w2)
{
    int e = blockIdx.z;
    int Ms = d_offsets[e], Me = d_offsets[e + 1];
    int M = Me - Ms;
    int m0 = blockIdx.y * 64;
    if (m0 >= M) return;
    __shared__ float As[16][68], Bs[16][68];
    int tid = threadIdx.x;
    int tx = tid & 15, ty = tid >> 4;
    int col0 = blockIdx.x * 64;
    int lr = tid >> 2, lv = tid & 3;
    int mrow = m0 + lr;
    const float* arow = (mrow < M) ? (h_buf + (size_t)(Ms + mrow) * Hh) : h_buf;
    const float4* Ap = (const float4*)arow + lv;
    const float4* Bp = (const float4*)(w2 + (size_t)e * Dd * Hh + (size_t)(col0 + lr) * Hh) + lv;
    float acc[4][4];
    #pragma unroll
    for (int i = 0; i < 4; i++)
        #pragma unroll
        for (int j = 0; j < 4; j++) acc[i][j] = 0.f;

    for (int k0 = 0; k0 < Hh / 4; k0 += 4) {
        float4 a = Ap[k0], b = Bp[k0];
        __syncthreads();
        As[lv*4+0][lr] = a.x; As[lv*4+1][lr] = a.y; As[lv*4+2][lr] = a.z; As[lv*4+3][lr] = a.w;
        Bs[lv*4+0][lr] = b.x; Bs[lv*4+1][lr] = b.y; Bs[lv*4+2][lr] = b.z; Bs[lv*4+3][lr] = b.w;
        __syncthreads();
        #pragma unroll
        for (int k = 0; k < 16; k++) {
            float4 av = *(const float4*)&As[k][ty * 4];
            float4 bv = *(const float4*)&Bs[k][tx * 4];
            float ar[4] = {av.x, av.y, av.z, av.w};
            float br[4] = {bv.x, bv.y, bv.z, bv.w};
            #pragma unroll
            for (int i = 0; i < 4; i++)
                #pragma unroll
                for (int j = 0; j < 4; j++) acc[i][j] += ar[i] * br[j];
        }
    }
    #pragma unroll
    for (int i = 0; i < 4; i++) {
        int m = m0 + ty * 4 + i;
        if (m < M) {
            int p = Ms + m;
            int slot = d_perm[p];
            float wk = d_top_w[slot];
            #pragma unroll
            for (int j = 0; j < 4; j++) {
                int c = col0 + tx * 4 + j;
                slot_out[(size_t)slot * Dd + c] = wk * acc[i][j];
            }
        }
    }
}

// out = shared (already in out) + slot0 + slot1   (fixed order -> deterministic)
__global__ void combine_kernel(float* __restrict__ out)
{
    int i = blockIdx.x * blockDim.x + threadIdx.x;   // float4 index, total T*D/4
    int e0 = i * 4;
    int t = e0 / Dd;
    int d = e0 - t * Dd;
    float4 o  = ((const float4*)out)[i];
    float4 s0 = *(const float4*)&slot_out[(size_t)(2 * t) * Dd + d];
    float4 s1 = *(const float4*)&slot_out[(size_t)(2 * t + 1) * Dd + d];
    o.x += s0.x + s1.x;
    o.y += s0.y + s1.y;
    o.z += s0.z + s1.z;
    o.w += s0.w + s1.w;
    ((float4*)out)[i] = o;
}

// ---------------- launch ----------------
extern "C" void kernel_launch(void* const* d_in, const int* in_sizes, int n_in,
                              void* d_out, int out_size)
{
    const float* x     = (const float*)d_in[0];
    const float* gatew = (const float*)d_in[1];
    const float* w1    = (const float*)d_in[2];
    const float* w2    = (const float*)d_in[3];
    const float* sfc1  = (const float*)d_in[4];
    const float* sfc2  = (const float*)d_in[5];
    const float* sfc3  = (const float*)d_in[6];
    float* out = (float*)d_out;

    // routing path
    zero_counts_kernel<<<1, 32>>>();
    router_kernel<<<T_TOK / 4, 128>>>(x, gatew);
    scan_kernel<<<1, 1>>>();
    scatter_kernel<<<(T_TOK * TOPK + 255) / 256, 256>>>();

    // shared expert
    shared_gemm1_kernel<<<dim3(Ss / 64, T_TOK / 64), 256>>>(x, sfc1, sfc2);
    shared_gemm2_kernel<<<dim3(Dd / 64, T_TOK / 64), 256>>>(sfc3, out);

    // sparse MoE (grouped by expert)
    moe_gemm1_kernel<<<dim3(Hh / 64, (T_TOK * TOPK) / 64, Ee), 256>>>(x, w1);
    moe_gemm2_kernel<<<dim3(Dd / 64, (T_TOK * TOPK) / 64, Ee), 256>>>(w2);

    // final combine
    combine_kernel<<<(T_TOK * Dd / 4) / 256, 256>>>(out);
}

// round 5
// speedup vs baseline: 2.1320x; 2.1320x over previous
#include <cuda_runtime.h>
#include <cuda_bf16.h>
#include <math.h>
#include <stdint.h>

// Problem constants
#define T_TOK 4096      // B*L tokens
#define Dd    1024      // model dim
#define Hh    512       // expert hidden
#define Ee    16        // num experts
#define Ss    2048      // shared expert hidden
#define TOPK  2

// ---------------- device scratch (no allocations allowed) ----------------
__device__ float g_buf[(size_t)T_TOK * Ss];
__device__ float h_buf[(size_t)T_TOK * TOPK * Hh];
__device__ float slot_out[(size_t)T_TOK * TOPK * Dd];
__device__ int   d_top_idx[T_TOK * TOPK];
__device__ float d_top_w[T_TOK * TOPK];
__device__ int   d_counts[Ee];
__device__ int   d_offsets[Ee + 1];
__device__ int   d_cursor[Ee];
__device__ int   d_perm[T_TOK * TOPK];

__device__ __forceinline__ float silu_f(float v) { return v / (1.0f + expf(-v)); }

__device__ __forceinline__ uint32_t smem_u32(const void* p) {
    uint32_t a;
    asm("{ .reg .u64 t; cvta.to.shared.u64 t, %1; cvt.u32.u64 %0, t; }" : "=r"(a) : "l"(p));
    return a;
}

// split float4 -> hi/lo bf16x2 pairs, store 8B to each array
__device__ __forceinline__ void sts_hilo(uint32_t a_hi, uint32_t a_lo, float4 f) {
    __nv_bfloat162 hxy = __floats2bfloat162_rn(f.x, f.y);
    __nv_bfloat162 hzw = __floats2bfloat162_rn(f.z, f.w);
    float lx = f.x - __bfloat162float(hxy.x);
    float ly = f.y - __bfloat162float(hxy.y);
    float lz = f.z - __bfloat162float(hzw.x);
    float lw = f.w - __bfloat162float(hzw.y);
    __nv_bfloat162 lxy = __floats2bfloat162_rn(lx, ly);
    __nv_bfloat162 lzw = __floats2bfloat162_rn(lz, lw);
    uint32_t h0 = *(uint32_t*)&hxy, h1 = *(uint32_t*)&hzw;
    uint32_t l0 = *(uint32_t*)&lxy, l1 = *(uint32_t*)&lzw;
    asm volatile("st.shared.v2.b32 [%0], {%1, %2};" :: "r"(a_hi), "r"(h0), "r"(h1));
    asm volatile("st.shared.v2.b32 [%0], {%1, %2};" :: "r"(a_lo), "r"(l0), "r"(l1));
}

__device__ __forceinline__ void ldsm_x4(uint32_t* r, uint32_t addr) {
    asm volatile("ldmatrix.sync.aligned.m8n8.x4.shared.b16 {%0,%1,%2,%3}, [%4];"
        : "=r"(r[0]), "=r"(r[1]), "=r"(r[2]), "=r"(r[3]) : "r"(addr));
}
__device__ __forceinline__ void ldsm_x2(uint32_t* r, uint32_t addr) {
    asm volatile("ldmatrix.sync.aligned.m8n8.x2.shared.b16 {%0,%1}, [%2];"
        : "=r"(r[0]), "=r"(r[1]) : "r"(addr));
}
__device__ __forceinline__ void mma16816(float* c, const uint32_t* a, const uint32_t* b) {
    asm volatile(
        "mma.sync.aligned.m16n8k16.row.col.f32.bf16.bf16.f32 "
        "{%0,%1,%2,%3}, {%4,%5,%6,%7}, {%8,%9}, {%0,%1,%2,%3};"
        : "+f"(c[0]), "+f"(c[1]), "+f"(c[2]), "+f"(c[3])
        : "r"(a[0]), "r"(a[1]), "r"(a[2]), "r"(a[3]), "r"(b[0]), "r"(b[1]));
}

// SMEM layout per buffer: AH@0, AL@10240, BH@20480, BL@30720 (128 rows x 80B each)
// two buffers, stride 40960. Total 81920 B.
#define SMEM_BYTES 81920

// ================= GEMM core: 128x128 tile, 8 warps (2x4), 64x32 warp tile ======
template <int NC, typename FA, typename FB, typename FE>
__device__ __forceinline__ void gemm_core(int tid, char* smem, FA loadA, FB loadB, FE epi)
{
    const int lane  = tid & 31;
    const int wid   = tid >> 5;
    const int warpM = wid >> 2;     // 0..1
    const int warpN = wid & 3;      // 0..3
    uint32_t sb = smem_u32(smem);
    const int lr = tid >> 1;        // row this thread loads (0..127)
    const int kb = (tid & 1) * 16;  // k base within chunk

    float acc[4][4][4];
    #pragma unroll
    for (int i = 0; i < 4; i++)
        #pragma unroll
        for (int t = 0; t < 4; t++)
            #pragma unroll
            for (int r = 0; r < 4; r++) acc[i][t][r] = 0.f;

    float4 va[4], vb[4];
    loadA(0, va);
    loadB(0, vb);
    {
        uint32_t ah = sb + (uint32_t)(lr * 80 + kb * 2);
        #pragma unroll
        for (int j = 0; j < 4; j++) {
            sts_hilo(ah + j * 8,          ah + 10240 + j * 8, va[j]);
            sts_hilo(ah + 20480 + j * 8,  ah + 30720 + j * 8, vb[j]);
        }
    }
    __syncthreads();

    const uint32_t arow  = (uint32_t)((warpM * 64 + (lane & 15)) * 80);
    const uint32_t brow  = (uint32_t)((warpN * 32 + (lane & 7)) * 80);
    const uint32_t akoff = (uint32_t)(((lane >> 4) & 1) * 16);
    const uint32_t bkoff = (uint32_t)(((lane >> 3) & 1) * 16);

    #pragma unroll 1
    for (int c = 0; c < NC; c++) {
        int p = c & 1;
        if (c + 1 < NC) { loadA(c + 1, va); loadB(c + 1, vb); }
        uint32_t bufb = sb + (uint32_t)p * 40960u;
        #pragma unroll
        for (int s = 0; s < 2; s++) {
            uint32_t ak = bufb + arow + (uint32_t)(s * 32) + akoff;
            uint32_t bk = bufb + 20480u + brow + (uint32_t)(s * 32) + bkoff;
            #pragma unroll
            for (int pr = 0; pr < 3; pr++) {
                uint32_t aoff = (pr == 2) ? 10240u : 0u;   // A_lo for product 2
                uint32_t boff = (pr == 1) ? 10240u : 0u;   // B_lo for product 1
                uint32_t af[4][4];
                #pragma unroll
                for (int i = 0; i < 4; i++) ldsm_x4(af[i], ak + aoff + (uint32_t)(i * 16 * 80));
                uint32_t bfr[4][2];
                #pragma unroll
                for (int t = 0; t < 4; t++) ldsm_x2(bfr[t], bk + boff + (uint32_t)(t * 8 * 80));
                #pragma unroll
                for (int i = 0; i < 4; i++)
                    #pragma unroll
                    for (int t = 0; t < 4; t++) mma16816(acc[i][t], af[i], bfr[t]);
            }
        }
        __syncthreads();
        if (c + 1 < NC) {
            uint32_t ah = sb + (uint32_t)(1 - p) * 40960u + (uint32_t)(lr * 80 + kb * 2);
            #pragma unroll
            for (int j = 0; j < 4; j++) {
                sts_hilo(ah + j * 8,         ah + 10240 + j * 8, va[j]);
                sts_hilo(ah + 20480 + j * 8, ah + 30720 + j * 8, vb[j]);
            }
            __syncthreads();
        }
    }
    epi(acc, warpM, warpN, lane);
}

// ---------------- routing ----------------
__global__ void zero_counts_kernel() {
    if (threadIdx.x < Ee) d_counts[threadIdx.x] = 0;
}

__global__ void router_kernel(const float* __restrict__ x, const float* __restrict__ gw) {
    int warp = threadIdx.x >> 5;
    int lane = threadIdx.x & 31;
    int t = blockIdx.x * 4 + warp;
    if (t >= T_TOK) return;
    const float* xr = x + (size_t)t * Dd;
    float logits[Ee];
    #pragma unroll 1
    for (int e = 0; e < Ee; e++) {
        const float* w = gw + (size_t)e * Dd;
        float p = 0.0f;
        for (int d = lane; d < Dd; d += 32) p += xr[d] * w[d];
        #pragma unroll
        for (int o = 16; o; o >>= 1) p += __shfl_down_sync(0xffffffffu, p, o);
        if (lane == 0) logits[e] = p;
    }
    if (lane == 0) {
        int i0 = 0; float v0 = logits[0];
        #pragma unroll
        for (int e = 1; e < Ee; e++) if (logits[e] > v0) { v0 = logits[e]; i0 = e; }
        int i1 = -1; float v1 = -3.0e38f;
        #pragma unroll
        for (int e = 0; e < Ee; e++) if (e != i0 && logits[e] > v1) { v1 = logits[e]; i1 = e; }
        float ex = expf(v1 - v0);
        float w0 = 1.0f / (1.0f + ex);
        float w1 = ex / (1.0f + ex);
        d_top_idx[2 * t]     = i0;
        d_top_idx[2 * t + 1] = i1;
        d_top_w[2 * t]       = w0;
        d_top_w[2 * t + 1]   = w1;
        atomicAdd(&d_counts[i0], 1);
        atomicAdd(&d_counts[i1], 1);
    }
}

__global__ void scan_kernel() {
    int o = 0;
    for (int e = 0; e < Ee; e++) { d_offsets[e] = o; d_cursor[e] = o; o += d_counts[e]; }
    d_offsets[Ee] = o;
}

__global__ void scatter_kernel() {
    int s = blockIdx.x * blockDim.x + threadIdx.x;
    if (s < T_TOK * TOPK) {
        int e = d_top_idx[s];
        int p = atomicAdd(&d_cursor[e], 1);
        d_perm[p] = s;
    }
}

// ================= GEMM kernels =================

// shared GEMM1: g_buf[:, c0:c0+64] = silu(x@sfc1^T) * (x@sfc2^T)
// B tile interleaves sfc1/sfc2 rows at 8-col granularity (q even->sfc1, odd->sfc2)
__global__ void __launch_bounds__(256) shared1_mm(
    const float* __restrict__ x, const float* __restrict__ s1, const float* __restrict__ s2)
{
    extern __shared__ char smem[];
    int tid = threadIdx.x;
    int row0 = blockIdx.y * 128;
    int c0g  = blockIdx.x * 64;
    int lr = tid >> 1, kb = (tid & 1) * 16;

    const float* abase = x + (size_t)(row0 + lr) * Dd + kb;
    int q = lr >> 3, nn = lr & 7;
    const float* bbase = ((q & 1) ? s2 : s1) + (size_t)(c0g + (q >> 1) * 8 + nn) * Dd + kb;

    auto loadA = [=](int c, float4* v) {
        #pragma unroll
        for (int j = 0; j < 4; j++) v[j] = *(const float4*)(abase + c * 32 + 4 * j);
    };
    auto loadB = [=](int c, float4* v) {
        #pragma unroll
        for (int j = 0; j < 4; j++) v[j] = *(const float4*)(bbase + c * 32 + 4 * j);
    };
    auto epi = [=](float acc[4][4][4], int warpM, int warpN, int lane) {
        int gid = lane >> 2, tig = lane & 3;
        #pragma unroll
        for (int i = 0; i < 4; i++) {
            int m = row0 + warpM * 64 + i * 16 + gid;
            #pragma unroll
            for (int j = 0; j < 2; j++) {
                int col = c0g + (warpN * 2 + j) * 8 + tig * 2;
                float* d0 = g_buf + (size_t)m * Ss + col;
                float* d1 = g_buf + (size_t)(m + 8) * Ss + col;
                float2 o0, o1;
                o0.x = silu_f(acc[i][2*j][0]) * acc[i][2*j+1][0];
                o0.y = silu_f(acc[i][2*j][1]) * acc[i][2*j+1][1];
                o1.x = silu_f(acc[i][2*j][2]) * acc[i][2*j+1][2];
                o1.y = silu_f(acc[i][2*j][3]) * acc[i][2*j+1][3];
                *(float2*)d0 = o0;
                *(float2*)d1 = o1;
            }
        }
    };
    gemm_core<Dd / 32>(tid, smem, loadA, loadB, epi);
}

// shared GEMM2: out = g_buf @ sfc3^T   (K = S)
__global__ void __launch_bounds__(256) shared2_mm(
    const float* __restrict__ s3, float* __restrict__ out)
{
    extern __shared__ char smem[];
    int tid = threadIdx.x;
    int row0 = blockIdx.y * 128;
    int col0 = blockIdx.x * 128;
    int lr = tid >> 1, kb = (tid & 1) * 16;

    const float* abase = g_buf + (size_t)(row0 + lr) * Ss + kb;
    const float* bbase = s3 + (size_t)(col0 + lr) * Ss + kb;

    auto loadA = [=](int c, float4* v) {
        #pragma unroll
        for (int j = 0; j < 4; j++) v[j] = *(const float4*)(abase + c * 32 + 4 * j);
    };
    auto loadB = [=](int c, float4* v) {
        #pragma unroll
        for (int j = 0; j < 4; j++) v[j] = *(const float4*)(bbase + c * 32 + 4 * j);
    };
    auto epi = [=](float acc[4][4][4], int warpM, int warpN, int lane) {
        int gid = lane >> 2, tig = lane & 3;
        #pragma unroll
        for (int i = 0; i < 4; i++) {
            int m = row0 + warpM * 64 + i * 16 + gid;
            #pragma unroll
            for (int t = 0; t < 4; t++) {
                int col = col0 + warpN * 32 + t * 8 + tig * 2;
                *(float2*)(out + (size_t)m * Dd + col)       = make_float2(acc[i][t][0], acc[i][t][1]);
                *(float2*)(out + (size_t)(m + 8) * Dd + col) = make_float2(acc[i][t][2], acc[i][t][3]);
            }
        }
    };
    gemm_core<Ss / 32>(tid, smem, loadA, loadB, epi);
}

// MoE GEMM1: h_buf[p] = silu(x[gather] @ w1[e]^T)
__global__ void __launch_bounds__(256) moe1_mm(
    const float* __restrict__ x, const float* __restrict__ w1)
{
    int e = blockIdx.z;
    int Ms = d_offsets[e], Me = d_offsets[e + 1];
    int M = Me - Ms;
    int m0 = blockIdx.y * 128;
    if (m0 >= M) return;

    extern __shared__ char smem[];
    int tid = threadIdx.x;
    int col0 = blockIdx.x * 128;
    int lr = tid >> 1, kb = (tid & 1) * 16;

    int mrow = m0 + lr;
    bool okA = (mrow < M);
    const float* abase = x + kb;
    if (okA) abase = x + (size_t)(d_perm[Ms + mrow] >> 1) * Dd + kb;
    const float* bbase = w1 + (size_t)e * Hh * Dd + (size_t)(col0 + lr) * Dd + kb;

    auto loadA = [=](int c, float4* v) {
        if (okA) {
            #pragma unroll
            for (int j = 0; j < 4; j++) v[j] = *(const float4*)(abase + c * 32 + 4 * j);
        } else {
            #pragma unroll
            for (int j = 0; j < 4; j++) v[j] = make_float4(0.f, 0.f, 0.f, 0.f);
        }
    };
    auto loadB = [=](int c, float4* v) {
        #pragma unroll
        for (int j = 0; j < 4; j++) v[j] = *(const float4*)(bbase + c * 32 + 4 * j);
    };
    auto epi = [=](float acc[4][4][4], int warpM, int warpN, int lane) {
        int gid = lane >> 2, tig = lane & 3;
        #pragma unroll
        for (int i = 0; i < 4; i++) {
            int mb = m0 + warpM * 64 + i * 16 + gid;
            #pragma unroll
            for (int t = 0; t < 4; t++) {
                int col = col0 + warpN * 32 + t * 8 + tig * 2;
                if (mb < M) {
                    float* d = h_buf + (size_t)(Ms + mb) * Hh + col;
                    *(float2*)d = make_float2(silu_f(acc[i][t][0]), silu_f(acc[i][t][1]));
                }
                if (mb + 8 < M) {
                    float* d = h_buf + (size_t)(Ms + mb + 8) * Hh + col;
                    *(float2*)d = make_float2(silu_f(acc[i][t][2]), silu_f(acc[i][t][3]));
                }
            }
        }
    };
    gemm_core<Dd / 32>(tid, smem, loadA, loadB, epi);
}

// MoE GEMM2: slot_out[slot] = wk * (h_buf @ w2[e]^T)
__global__ void __launch_bounds__(256) moe2_mm(const float* __restrict__ w2)
{
    int e = blockIdx.z;
    int Ms = d_offsets[e], Me = d_offsets[e + 1];
    int M = Me - Ms;
    int m0 = blockIdx.y * 128;
    if (m0 >= M) return;

    extern __shared__ char smem[];
    int tid = threadIdx.x;
    int col0 = blockIdx.x * 128;
    int lr = tid >> 1, kb = (tid & 1) * 16;

    int mrow = m0 + lr;
    bool okA = (mrow < M);
    const float* abase = h_buf + kb;
    if (okA) abase = h_buf + (size_t)(Ms + mrow) * Hh + kb;
    const float* bbase = w2 + (size_t)e * Dd * Hh + (size_t)(col0 + lr) * Hh + kb;

    auto loadA = [=](int c, float4* v) {
        if (okA) {
            #pragma unroll
            for (int j = 0; j < 4; j++) v[j] = *(const float4*)(abase + c * 32 + 4 * j);
        } else {
            #pragma unroll
            for (int j = 0; j < 4; j++) v[j] = make_float4(0.f, 0.f, 0.f, 0.f);
        }
    };
    auto loadB = [=](int c, float4* v) {
        #pragma unroll
        for (int j = 0; j < 4; j++) v[j] = *(const float4*)(bbase + c * 32 + 4 * j);
    };
    auto epi = [=](float acc[4][4][4], int warpM, int warpN, int lane) {
        int gid = lane >> 2, tig = lane & 3;
        #pragma unroll
        for (int i = 0; i < 4; i++) {
            int mb = m0 + warpM * 64 + i * 16 + gid;
            #pragma unroll
            for (int t = 0; t < 4; t++) {
                int col = col0 + warpN * 32 + t * 8 + tig * 2;
                if (mb < M) {
                    int slot = d_perm[Ms + mb];
                    float wk = d_top_w[slot];
                    float* d = slot_out + (size_t)slot * Dd + col;
                    *(float2*)d = make_float2(wk * acc[i][t][0], wk * acc[i][t][1]);
                }
                if (mb + 8 < M) {
                    int slot = d_perm[Ms + mb + 8];
                    float wk = d_top_w[slot];
                    float* d = slot_out + (size_t)slot * Dd + col;
                    *(float2*)d = make_float2(wk * acc[i][t][2], wk * acc[i][t][3]);
                }
            }
        }
    };
    gemm_core<Hh / 32>(tid, smem, loadA, loadB, epi);
}

// out = shared (already in out) + slot0 + slot1
__global__ void combine_kernel(float* __restrict__ out)
{
    int i = blockIdx.x * blockDim.x + threadIdx.x;
    int e0 = i * 4;
    int t = e0 / Dd;
    int d = e0 - t * Dd;
    float4 o  = ((const float4*)out)[i];
    float4 s0 = *(const float4*)&slot_out[(size_t)(2 * t) * Dd + d];
    float4 s1 = *(const float4*)&slot_out[(size_t)(2 * t + 1) * Dd + d];
    o.x += s0.x + s1.x;
    o.y += s0.y + s1.y;
    o.z += s0.z + s1.z;
    o.w += s0.w + s1.w;
    ((float4*)out)[i] = o;
}

// ---------------- launch ----------------
extern "C" void kernel_launch(void* const* d_in, const int* in_sizes, int n_in,
                              void* d_out, int out_size)
{
    const float* x     = (const float*)d_in[0];
    const float* gatew = (const float*)d_in[1];
    const float* w1    = (const float*)d_in[2];
    const float* w2    = (const float*)d_in[3];
    const float* sfc1  = (const float*)d_in[4];
    const float* sfc2  = (const float*)d_in[5];
    const float* sfc3  = (const float*)d_in[6];
    float* out = (float*)d_out;

    cudaFuncSetAttribute(shared1_mm, cudaFuncAttributeMaxDynamicSharedMemorySize, SMEM_BYTES);
    cudaFuncSetAttribute(shared2_mm, cudaFuncAttributeMaxDynamicSharedMemorySize, SMEM_BYTES);
    cudaFuncSetAttribute(moe1_mm,    cudaFuncAttributeMaxDynamicSharedMemorySize, SMEM_BYTES);
    cudaFuncSetAttribute(moe2_mm,    cudaFuncAttributeMaxDynamicSharedMemorySize, SMEM_BYTES);

    // routing path
    zero_counts_kernel<<<1, 32>>>();
    router_kernel<<<T_TOK / 4, 128>>>(x, gatew);
    scan_kernel<<<1, 1>>>();
    scatter_kernel<<<(T_TOK * TOPK + 255) / 256, 256>>>();

    // shared expert (tensor cores via mma.sync)
    shared1_mm<<<dim3(Ss / 64, T_TOK / 128), 256, SMEM_BYTES>>>(x, sfc1, sfc2);
    shared2_mm<<<dim3(Dd / 128, T_TOK / 128), 256, SMEM_BYTES>>>(sfc3, out);

    // sparse MoE (grouped by expert)
    moe1_mm<<<dim3(Hh / 128, (T_TOK * TOPK) / 128, Ee), 256, SMEM_BYTES>>>(x, w1);
    moe2_mm<<<dim3(Dd / 128, (T_TOK * TOPK) / 128, Ee), 256, SMEM_BYTES>>>(w2);

    // final combine
    combine_kernel<<<(T_TOK * Dd / 4) / 256, 256>>>(out);
}

// round 7
// speedup vs baseline: 2.1918x; 1.0281x over previous
#include <cuda_runtime.h>
#include <cuda_bf16.h>
#include <math.h>
#include <stdint.h>

// Problem constants
#define T_TOK 4096      // B*L tokens
#define Dd    1024      // model dim
#define Hh    512       // expert hidden
#define Ee    16        // num experts
#define Ss    2048      // shared expert hidden
#define TOPK  2

// ---------------- device scratch (no allocations allowed) ----------------
// pre-split bf16 hi/lo operand arrays (uint32 = bf16x2, element-pair granularity)
__device__ uint32_t xs_hi[(size_t)T_TOK * Dd / 2],  xs_lo[(size_t)T_TOK * Dd / 2];
__device__ uint32_t w1s_hi[(size_t)Ee * Hh * Dd / 2], w1s_lo[(size_t)Ee * Hh * Dd / 2];
__device__ uint32_t w2s_hi[(size_t)Ee * Dd * Hh / 2], w2s_lo[(size_t)Ee * Dd * Hh / 2];
__device__ uint32_t s1s_hi[(size_t)Ss * Dd / 2], s1s_lo[(size_t)Ss * Dd / 2];
__device__ uint32_t s2s_hi[(size_t)Ss * Dd / 2], s2s_lo[(size_t)Ss * Dd / 2];
__device__ uint32_t s3s_hi[(size_t)Dd * Ss / 2], s3s_lo[(size_t)Dd * Ss / 2];
__device__ uint32_t g_hi[(size_t)T_TOK * Ss / 2], g_lo[(size_t)T_TOK * Ss / 2];
__device__ uint32_t h_hi[(size_t)T_TOK * TOPK * Hh / 2], h_lo[(size_t)T_TOK * TOPK * Hh / 2];
__device__ float slot_out[(size_t)T_TOK * TOPK * Dd];
__device__ int   d_top_idx[T_TOK * TOPK];
__device__ float d_top_w[T_TOK * TOPK];
__device__ int   d_counts[Ee];
__device__ int   d_offsets[Ee + 1];
__device__ int   d_cursor[Ee];
__device__ int   d_perm[T_TOK * TOPK];

__device__ __forceinline__ float silu_f(float v) { return v / (1.0f + expf(-v)); }

__device__ __forceinline__ uint32_t smem_u32(const void* p) {
    uint32_t a;
    asm("{ .reg .u64 t; cvta.to.shared.u64 t, %1; cvt.u32.u64 %0, t; }" : "=r"(a) : "l"(p));
    return a;
}

// pack 2 floats into hi/lo bf16x2 words
__device__ __forceinline__ void pack2_hilo(float a, float b, uint32_t& hi, uint32_t& lo) {
    __nv_bfloat162 h = __floats2bfloat162_rn(a, b);
    float ra = a - __bfloat162float(h.x);
    float rb = b - __bfloat162float(h.y);
    __nv_bfloat162 l = __floats2bfloat162_rn(ra, rb);
    hi = *(uint32_t*)&h;
    lo = *(uint32_t*)&l;
}

__device__ __forceinline__ void ldsm_x4(uint32_t* r, uint32_t addr) {
    asm volatile("ldmatrix.sync.aligned.m8n8.x4.shared.b16 {%0,%1,%2,%3}, [%4];"
        : "=r"(r[0]), "=r"(r[1]), "=r"(r[2]), "=r"(r[3]) : "r"(addr));
}
__device__ __forceinline__ void ldsm_x2(uint32_t* r, uint32_t addr) {
    asm volatile("ldmatrix.sync.aligned.m8n8.x2.shared.b16 {%0,%1}, [%2];"
        : "=r"(r[0]), "=r"(r[1]) : "r"(addr));
}
__device__ __forceinline__ void mma16816(float* c, const uint32_t* a, const uint32_t* b) {
    asm volatile(
        "mma.sync.aligned.m16n8k16.row.col.f32.bf16.bf16.f32 "
        "{%0,%1,%2,%3}, {%4,%5,%6,%7}, {%8,%9}, {%0,%1,%2,%3};"
        : "+f"(c[0]), "+f"(c[1]), "+f"(c[2]), "+f"(c[3])
        : "r"(a[0]), "r"(a[1]), "r"(a[2]), "r"(a[3]), "r"(b[0]), "r"(b[1]));
}

__device__ __forceinline__ void cp16(uint32_t dst, const void* src, int sz) {
    asm volatile("cp.async.cg.shared.global [%0], [%1], 16, %2;"
                 :: "r"(dst), "l"(src), "r"(sz) : "memory");
}
#define CP_COMMIT() asm volatile("cp.async.commit_group;" ::: "memory")
#define CP_WAIT0()  asm volatile("cp.async.wait_group 0;" ::: "memory")
#define CP_WAIT1()  asm volatile("cp.async.wait_group 1;" ::: "memory")

// SMEM per buffer: AH@0, AL@10240, BH@20480, BL@30720 (128 rows x 80B each).
// two buffers, stride 40960. Total 81920 B.
#define SMEM_BYTES 81920

// ====== GEMM core: 128x128 tile, 8 warps (2x4), 64x32 warp tile, cp.async x2 ======
// aHi/aLo/bHi/bLo: per-thread global src (row + 32B-half adjusted); chunk c at +c*64B.
template <int NC, typename FE>
__device__ __forceinline__ void gemm_core(
    int tid, char* smem,
    const char* aHi, const char* aLo, int szA,
    const char* bHi, const char* bLo, FE epi)
{
    const int lane  = tid & 31;
    const int wid   = tid >> 5;
    const int warpM = wid >> 2;
    const int warpN = wid & 3;
    uint32_t sb = smem_u32(smem);
    const int lr = tid >> 1;
    uint32_t dstBase = sb + (uint32_t)(lr * 80 + (tid & 1) * 32);

    float acc[4][4][4];
    #pragma unroll
    for (int i = 0; i < 4; i++)
        #pragma unroll
        for (int t = 0; t < 4; t++)
            #pragma unroll
            for (int r = 0; r < 4; r++) acc[i][t][r] = 0.f;

    auto issue = [&](int c, int buf) {
        uint32_t d = dstBase + (uint32_t)buf * 40960u;
        const char* pAh = aHi + (size_t)c * 64;
        const char* pAl = aLo + (size_t)c * 64;
        const char* pBh = bHi + (size_t)c * 64;
        const char* pBl = bLo + (size_t)c * 64;
        cp16(d,              pAh,      szA); cp16(d + 16,         pAh + 16, szA);
        cp16(d + 10240,      pAl,      szA); cp16(d + 10240 + 16, pAl + 16, szA);
        cp16(d + 20480,      pBh,      16);  cp16(d + 20480 + 16, pBh + 16, 16);
        cp16(d + 30720,      pBl,      16);  cp16(d + 30720 + 16, pBl + 16, 16);
    };

    issue(0, 0);
    CP_COMMIT();

    const uint32_t arow  = (uint32_t)((warpM * 64 + (lane & 15)) * 80);
    const uint32_t brow  = (uint32_t)((warpN * 32 + (lane & 7)) * 80);
    const uint32_t akoff = (uint32_t)(((lane >> 4) & 1) * 16);
    const uint32_t bkoff = (uint32_t)(((lane >> 3) & 1) * 16);

    #pragma unroll 1
    for (int c = 0; c < NC; c++) {
        if (c + 1 < NC) { issue(c + 1, (c + 1) & 1); CP_COMMIT(); CP_WAIT1(); }
        else            { CP_WAIT0(); }
        __syncthreads();
        uint32_t bufb = sb + (uint32_t)(c & 1) * 40960u;
        #pragma unroll
        for (int s = 0; s < 2; s++) {
            uint32_t ak = bufb + arow + (uint32_t)(s * 32) + akoff;
            uint32_t bk = bufb + 20480u + brow + (uint32_t)(s * 32) + bkoff;
            uint32_t ah[4][4], al[4][4], bh[4][2], bl[4][2];
            #pragma unroll
            for (int i = 0; i < 4; i++) {
                ldsm_x4(ah[i], ak          + (uint32_t)(i * 16 * 80));
                ldsm_x4(al[i], ak + 10240u + (uint32_t)(i * 16 * 80));
            }
            #pragma unroll
            for (int t = 0; t < 4; t++) {
                ldsm_x2(bh[t], bk          + (uint32_t)(t * 8 * 80));
                ldsm_x2(bl[t], bk + 10240u + (uint32_t)(t * 8 * 80));
            }
            #pragma unroll
            for (int i = 0; i < 4; i++)
                #pragma unroll
                for (int t = 0; t < 4; t++) mma16816(acc[i][t], ah[i], bh[t]);
            #pragma unroll
            for (int i = 0; i < 4; i++)
                #pragma unroll
                for (int t = 0; t < 4; t++) mma16816(acc[i][t], ah[i], bl[t]);
            #pragma unroll
            for (int i = 0; i < 4; i++)
                #pragma unroll
                for (int t = 0; t < 4; t++) mma16816(acc[i][t], al[i], bh[t]);
        }
        __syncthreads();
    }
    epi(acc, warpM, warpN, lane);
}

// ---------------- operand pre-split ----------------
__global__ void split_kernel(const float* __restrict__ in, uint32_t* __restrict__ hi,
                             uint32_t* __restrict__ lo, int n2)
{
    int i = blockIdx.x * blockDim.x + threadIdx.x;
    if (i < n2) {
        float2 v = ((const float2*)in)[i];
        uint32_t h, l;
        pack2_hilo(v.x, v.y, h, l);
        hi[i] = h;
        lo[i] = l;
    }
}

// ---------------- routing ----------------
__global__ void zero_counts_kernel() {
    if (threadIdx.x < Ee) d_counts[threadIdx.x] = 0;
}

__global__ void router_kernel(const float* __restrict__ x, const float* __restrict__ gw) {
    int warp = threadIdx.x >> 5;
    int lane = threadIdx.x & 31;
    int t = blockIdx.x * 4 + warp;
    if (t >= T_TOK) return;
    const float* xr = x + (size_t)t * Dd;
    float logits[Ee];
    #pragma unroll 1
    for (int e = 0; e < Ee; e++) {
        const float* w = gw + (size_t)e * Dd;
        float p = 0.0f;
        for (int d = lane; d < Dd; d += 32) p += xr[d] * w[d];
        #pragma unroll
        for (int o = 16; o; o >>= 1) p += __shfl_down_sync(0xffffffffu, p, o);
        if (lane == 0) logits[e] = p;
    }
    if (lane == 0) {
        int i0 = 0; float v0 = logits[0];
        #pragma unroll
        for (int e = 1; e < Ee; e++) if (logits[e] > v0) { v0 = logits[e]; i0 = e; }
        int i1 = -1; float v1 = -3.0e38f;
        #pragma unroll
        for (int e = 0; e < Ee; e++) if (e != i0 && logits[e] > v1) { v1 = logits[e]; i1 = e; }
        float ex = expf(v1 - v0);
        float w0 = 1.0f / (1.0f + ex);
        float w1 = ex / (1.0f + ex);
        d_top_idx[2 * t]     = i0;
        d_top_idx[2 * t + 1] = i1;
        d_top_w[2 * t]       = w0;
        d_top_w[2 * t + 1]   = w1;
        atomicAdd(&d_counts[i0], 1);
        atomicAdd(&d_counts[i1], 1);
    }
}

__global__ void scan_kernel() {
    int o = 0;
    for (int e = 0; e < Ee; e++) { d_offsets[e] = o; d_cursor[e] = o; o += d_counts[e]; }
    d_offsets[Ee] = o;
}

__global__ void scatter_kernel() {
    int s = blockIdx.x * blockDim.x + threadIdx.x;
    if (s < T_TOK * TOPK) {
        int e = d_top_idx[s];
        int p = atomicAdd(&d_cursor[e], 1);
        d_perm[p] = s;
    }
}

// ================= GEMM kernels =================

// shared GEMM1: g[:, c0:c0+64] = silu(x@sfc1^T) * (x@sfc2^T)  (dual-B, interleaved rows)
__global__ void __launch_bounds__(256) shared1_mm()
{
    extern __shared__ char smem[];
    int tid = threadIdx.x;
    int row0 = blockIdx.y * 128;
    int c0g  = blockIdx.x * 64;
    int lr = tid >> 1, hb = (tid & 1) * 32;

    const char* aHi = (const char*)xs_hi + (size_t)(row0 + lr) * (Dd * 2) + hb;
    const char* aLo = (const char*)xs_lo + (size_t)(row0 + lr) * (Dd * 2) + hb;
    int q = lr >> 3, nn = lr & 7;
    size_t brow = (size_t)(c0g + (q >> 1) * 8 + nn) * (Dd * 2) + hb;
    const char* bHi = (const char*)((q & 1) ? s2s_hi : s1s_hi) + brow;
    const char* bLo = (const char*)((q & 1) ? s2s_lo : s1s_lo) + brow;

    auto epi = [=](float acc[4][4][4], int warpM, int warpN, int lane) {
        int gid = lane >> 2, tig = lane & 3;
        #pragma unroll
        for (int i = 0; i < 4; i++) {
            int m = row0 + warpM * 64 + i * 16 + gid;
            #pragma unroll
            for (int j = 0; j < 2; j++) {
                int col = c0g + (warpN * 2 + j) * 8 + tig * 2;
                uint32_t h, l;
                size_t idx0 = (size_t)m * (Ss / 2) + (col >> 1);
                pack2_hilo(silu_f(acc[i][2*j][0]) * acc[i][2*j+1][0],
                           silu_f(acc[i][2*j][1]) * acc[i][2*j+1][1], h, l);
                g_hi[idx0] = h; g_lo[idx0] = l;
                size_t idx1 = (size_t)(m + 8) * (Ss / 2) + (col >> 1);
                pack2_hilo(silu_f(acc[i][2*j][2]) * acc[i][2*j+1][2],
                           silu_f(acc[i][2*j][3]) * acc[i][2*j+1][3], h, l);
                g_hi[idx1] = h; g_lo[idx1] = l;
            }
        }
    };
    gemm_core<Dd / 32>(tid, smem, aHi, aLo, 16, bHi, bLo, epi);
}

// shared GEMM2: out = g @ sfc3^T  (K = S)
__global__ void __launch_bounds__(256) shared2_mm(float* __restrict__ out)
{
    extern __shared__ char smem[];
    int tid = threadIdx.x;
    int row0 = blockIdx.y * 128;
    int col0 = blockIdx.x * 128;
    int lr = tid >> 1, hb = (tid & 1) * 32;

    const char* aHi = (const char*)g_hi + (size_t)(row0 + lr) * (Ss * 2) + hb;
    const char* aLo = (const char*)g_lo + (size_t)(row0 + lr) * (Ss * 2) + hb;
    const char* bHi = (const char*)s3s_hi + (size_t)(col0 + lr) * (Ss * 2) + hb;
    const char* bLo = (const char*)s3s_lo + (size_t)(col0 + lr) * (Ss * 2) + hb;

    auto epi = [=](float acc[4][4][4], int warpM, int warpN, int lane) {
        int gid = lane >> 2, tig = lane & 3;
        #pragma unroll
        for (int i = 0; i < 4; i++) {
            int m = row0 + warpM * 64 + i * 16 + gid;
            #pragma unroll
            for (int t = 0; t < 4; t++) {
                int col = col0 + warpN * 32 + t * 8 + tig * 2;
                *(float2*)(out + (size_t)m * Dd + col)       = make_float2(acc[i][t][0], acc[i][t][1]);
                *(float2*)(out + (size_t)(m + 8) * Dd + col) = make_float2(acc[i][t][2], acc[i][t][3]);
            }
        }
    };
    gemm_core<Ss / 32>(tid, smem, aHi, aLo, 16, bHi, bLo, epi);
}

// MoE GEMM1: h[p] = silu(x[gather] @ w1[e]^T)
__global__ void __launch_bounds__(256) moe1_mm()
{
    int e = blockIdx.z;
    int Ms = d_offsets[e], Me = d_offsets[e + 1];
    int M = Me - Ms;
    int m0 = blockIdx.y * 128;
    if (m0 >= M) return;

    extern __shared__ char smem[];
    int tid = threadIdx.x;
    int col0 = blockIdx.x * 128;
    int lr = tid >> 1, hb = (tid & 1) * 32;

    int mrow = m0 + lr;
    bool okA = (mrow < M);
    int tok = okA ? (d_perm[Ms + mrow] >> 1) : 0;
    const char* aHi = (const char*)xs_hi + (size_t)tok * (Dd * 2) + hb;
    const char* aLo = (const char*)xs_lo + (size_t)tok * (Dd * 2) + hb;
    const char* bHi = (const char*)w1s_hi + ((size_t)e * Hh + col0 + lr) * (Dd * 2) + hb;
    const char* bLo = (const char*)w1s_lo + ((size_t)e * Hh + col0 + lr) * (Dd * 2) + hb;

    auto epi = [=](float acc[4][4][4], int warpM, int warpN, int lane) {
        int gid = lane >> 2, tig = lane & 3;
        #pragma unroll
        for (int i = 0; i < 4; i++) {
            int mb = m0 + warpM * 64 + i * 16 + gid;
            #pragma unroll
            for (int t = 0; t < 4; t++) {
                int col = col0 + warpN * 32 + t * 8 + tig * 2;
                uint32_t h, l;
                if (mb < M) {
                    size_t idx = (size_t)(Ms + mb) * (Hh / 2) + (col >> 1);
                    pack2_hilo(silu_f(acc[i][t][0]), silu_f(acc[i][t][1]), h, l);
                    h_hi[idx] = h; h_lo[idx] = l;
                }
                if (mb + 8 < M) {
                    size_t idx = (size_t)(Ms + mb + 8) * (Hh / 2) + (col >> 1);
                    pack2_hilo(silu_f(acc[i][t][2]), silu_f(acc[i][t][3]), h, l);
                    h_hi[idx] = h; h_lo[idx] = l;
                }
            }
        }
    };
    gemm_core<Dd / 32>(tid, smem, aHi, aLo, okA ? 16 : 0, bHi, bLo, epi);
}

// MoE GEMM2: slot_out[slot] = wk * (h @ w2[e]^T)
__global__ void __launch_bounds__(256) moe2_mm()
{
    int e = blockIdx.z;
    int Ms = d_offsets[e], Me = d_offsets[e + 1];
    int M = Me - Ms;
    int m0 = blockIdx.y * 128;
    if (m0 >= M) return;

    extern __shared__ char smem[];
    int tid = threadIdx.x;
    int col0 = blockIdx.x * 128;
    int lr = tid >> 1, hb = (tid & 1) * 32;

    int mrow = m0 + lr;
    bool okA = (mrow < M);
    size_t arow = (size_t)(Ms + (okA ? mrow : 0)) * (Hh * 2) + hb;
    const char* aHi = (const char*)h_hi + arow;
    const char* aLo = (const char*)h_lo + arow;
    const char* bHi = (const char*)w2s_hi + ((size_t)e * Dd + col0 + lr) * (Hh * 2) + hb;
    const char* bLo = (const char*)w2s_lo + ((size_t)e * Dd + col0 + lr) * (Hh * 2) + hb;

    auto epi = [=](float acc[4][4][4], int warpM, int warpN, int lane) {
        int gid = lane >> 2, tig = lane & 3;
        #pragma unroll
        for (int i = 0; i < 4; i++) {
            int mb = m0 + warpM * 64 + i * 16 + gid;
            #pragma unroll
            for (int t = 0; t < 4; t++) {
                int col = col0 + warpN * 32 + t * 8 + tig * 2;
                if (mb < M) {
                    int slot = d_perm[Ms + mb];
                    float wk = d_top_w[slot];
                    *(float2*)(slot_out + (size_t)slot * Dd + col) =
                        make_float2(wk * acc[i][t][0], wk * acc[i][t][1]);
                }
                if (mb + 8 < M) {
                    int slot = d_perm[Ms + mb + 8];
                    float wk = d_top_w[slot];
                    *(float2*)(slot_out + (size_t)slot * Dd + col) =
                        make_float2(wk * acc[i][t][2], wk * acc[i][t][3]);
                }
            }
        }
    };
    gemm_core<Hh / 32>(tid, smem, aHi, aLo, okA ? 16 : 0, bHi, bLo, epi);
}

// out = shared (already in out) + slot0 + slot1
__global__ void combine_kernel(float* __restrict__ out)
{
    int i = blockIdx.x * blockDim.x + threadIdx.x;
    int e0 = i * 4;
    int t = e0 / Dd;
    int d = e0 - t * Dd;
    float4 o  = ((const float4*)out)[i];
    float4 s0 = *(const float4*)&slot_out[(size_t)(2 * t) * Dd + d];
    float4 s1 = *(const float4*)&slot_out[(size_t)(2 * t + 1) * Dd + d];
    o.x += s0.x + s1.x;
    o.y += s0.y + s1.y;
    o.z += s0.z + s1.z;
    o.w += s0.w + s1.w;
    ((float4*)out)[i] = o;
}

// ---------------- launch ----------------
extern "C" void kernel_launch(void* const* d_in, const int* in_sizes, int n_in,
                              void* d_out, int out_size)
{
    const float* x     = (const float*)d_in[0];
    const float* gatew = (const float*)d_in[1];
    const float* w1    = (const float*)d_in[2];
    const float* w2    = (const float*)d_in[3];
    const float* sfc1  = (const float*)d_in[4];
    const float* sfc2  = (const float*)d_in[5];
    const float* sfc3  = (const float*)d_in[6];
    float* out = (float*)d_out;

    cudaFuncSetAttribute(shared1_mm, cudaFuncAttributeMaxDynamicSharedMemorySize, SMEM_BYTES);
    cudaFuncSetAttribute(shared2_mm, cudaFuncAttributeMaxDynamicSharedMemorySize, SMEM_BYTES);
    cudaFuncSetAttribute(moe1_mm,    cudaFuncAttributeMaxDynamicSharedMemorySize, SMEM_BYTES);
    cudaFuncSetAttribute(moe2_mm,    cudaFuncAttributeMaxDynamicSharedMemorySize, SMEM_BYTES);

    uint32_t *p_xh, *p_xl, *p_w1h, *p_w1l, *p_w2h, *p_w2l;
    uint32_t *p_s1h, *p_s1l, *p_s2h, *p_s2l, *p_s3h, *p_s3l;
    cudaGetSymbolAddress((void**)&p_xh,  xs_hi);  cudaGetSymbolAddress((void**)&p_xl,  xs_lo);
    cudaGetSymbolAddress((void**)&p_w1h, w1s_hi); cudaGetSymbolAddress((void**)&p_w1l, w1s_lo);
    cudaGetSymbolAddress((void**)&p_w2h, w2s_hi); cudaGetSymbolAddress((void**)&p_w2l, w2s_lo);
    cudaGetSymbolAddress((void**)&p_s1h, s1s_hi); cudaGetSymbolAddress((void**)&p_s1l, s1s_lo);
    cudaGetSymbolAddress((void**)&p_s2h, s2s_hi); cudaGetSymbolAddress((void**)&p_s2l, s2s_lo);
    cudaGetSymbolAddress((void**)&p_s3h, s3s_hi); cudaGetSymbolAddress((void**)&p_s3l, s3s_lo);

    // routing path
    zero_counts_kernel<<<1, 32>>>();
    router_kernel<<<T_TOK / 4, 128>>>(x, gatew);
    scan_kernel<<<1, 1>>>();
    scatter_kernel<<<(T_TOK * TOPK + 255) / 256, 256>>>();

    // operand pre-split (fp32 -> bf16 hi/lo)
    {
        int n2;
        n2 = T_TOK * Dd / 2;     split_kernel<<<(n2 + 255) / 256, 256>>>(x,    p_xh,  p_xl,  n2);
        n2 = Ee * Hh * Dd / 2;   split_kernel<<<(n2 + 255) / 256, 256>>>(w1,   p_w1h, p_w1l, n2);
        n2 = Ee * Dd * Hh / 2;   split_kernel<<<(n2 + 255) / 256, 256>>>(w2,   p_w2h, p_w2l, n2);
        n2 = Ss * Dd / 2;        split_kernel<<<(n2 + 255) / 256, 256>>>(sfc1, p_s1h, p_s1l, n2);
        n2 = Ss * Dd / 2;        split_kernel<<<(n2 + 255) / 256, 256>>>(sfc2, p_s2h, p_s2l, n2);
        n2 = Dd * Ss / 2;        split_kernel<<<(n2 + 255) / 256, 256>>>(sfc3, p_s3h, p_s3l, n2);
    }

    // shared expert
    shared1_mm<<<dim3(Ss / 64, T_TOK / 128), 256, SMEM_BYTES>>>();
    shared2_mm<<<dim3(Dd / 128, T_TOK / 128), 256, SMEM_BYTES>>>(out);

    // sparse MoE (grouped by expert)
    moe1_mm<<<dim3(Hh / 128, (T_TOK * TOPK) / 128, Ee), 256, SMEM_BYTES>>>();
    moe2_mm<<<dim3(Dd / 128, (T_TOK * TOPK) / 128, Ee), 256, SMEM_BYTES>>>();

    // final combine
    combine_kernel<<<(T_TOK * Dd / 4) / 256, 256>>>(out);
}

// round 11
// speedup vs baseline: 2.8546x; 1.3024x over previous
#include <cuda_runtime.h>
#include <cuda_fp16.h>
#include <math.h>
#include <stdint.h>

// Problem constants
#define T_TOK 4096      // B*L tokens
#define Dd    1024      // model dim
#define Hh    512       // expert hidden
#define Ee    16        // num experts
#define Ss    2048      // shared expert hidden
#define TOPK  2

// ---------------- device scratch (no allocations allowed) ----------------
// A-side operands: fp16 hi/lo split (uint32 = half2). B-side: single fp16.
__device__ uint32_t xs_hi[(size_t)T_TOK * Dd / 2],  xs_lo[(size_t)T_TOK * Dd / 2];
__device__ uint32_t w1s[(size_t)Ee * Hh * Dd / 2];
__device__ uint32_t w2s[(size_t)Ee * Dd * Hh / 2];
__device__ uint32_t s1s[(size_t)Ss * Dd / 2];
__device__ uint32_t s2s[(size_t)Ss * Dd / 2];
__device__ uint32_t s3s[(size_t)Dd * Ss / 2];
__device__ uint32_t g_hi[(size_t)T_TOK * Ss / 2], g_lo[(size_t)T_TOK * Ss / 2];
__device__ uint32_t h_hi[(size_t)T_TOK * TOPK * Hh / 2], h_lo[(size_t)T_TOK * TOPK * Hh / 2];
__device__ float slot_out[(size_t)T_TOK * TOPK * Dd];
__device__ int   d_top_idx[T_TOK * TOPK];
__device__ float d_top_w[T_TOK * TOPK];
__device__ int   d_counts[Ee];
__device__ int   d_offsets[Ee + 1];
__device__ int   d_cursor[Ee];
__device__ int   d_perm[T_TOK * TOPK];

__device__ __forceinline__ float silu_f(float v) { return v / (1.0f + expf(-v)); }

__device__ __forceinline__ uint32_t smem_u32(const void* p) {
    uint32_t a;
    asm("{ .reg .u64 t; cvta.to.shared.u64 t, %1; cvt.u32.u64 %0, t; }" : "=r"(a) : "l"(p));
    return a;
}

// pack 2 floats into fp16 hi/lo half2 words
__device__ __forceinline__ void pack2_hilo(float a, float b, uint32_t& hi, uint32_t& lo) {
    __half2 h = __floats2half2_rn(a, b);
    float ra = a - __half2float(h.x);
    float rb = b - __half2float(h.y);
    __half2 l = __floats2half2_rn(ra, rb);
    hi = *(uint32_t*)&h;
    lo = *(uint32_t*)&l;
}
__device__ __forceinline__ uint32_t pack2_single(float a, float b) {
    __half2 h = __floats2half2_rn(a, b);
    return *(uint32_t*)&h;
}

__device__ __forceinline__ void ldsm_x4(uint32_t* r, uint32_t addr) {
    asm volatile("ldmatrix.sync.aligned.m8n8.x4.shared.b16 {%0,%1,%2,%3}, [%4];"
        : "=r"(r[0]), "=r"(r[1]), "=r"(r[2]), "=r"(r[3]) : "r"(addr));
}
__device__ __forceinline__ void ldsm_x2(uint32_t* r, uint32_t addr) {
    asm volatile("ldmatrix.sync.aligned.m8n8.x2.shared.b16 {%0,%1}, [%2];"
        : "=r"(r[0]), "=r"(r[1]) : "r"(addr));
}
__device__ __forceinline__ void mma16816(float* c, const uint32_t* a, const uint32_t* b) {
    asm volatile(
        "mma.sync.aligned.m16n8k16.row.col.f32.f16.f16.f32 "
        "{%0,%1,%2,%3}, {%4,%5,%6,%7}, {%8,%9}, {%0,%1,%2,%3};"
        : "+f"(c[0]), "+f"(c[1]), "+f"(c[2]), "+f"(c[3])
        : "r"(a[0]), "r"(a[1]), "r"(a[2]), "r"(a[3]), "r"(b[0]), "r"(b[1]));
}

__device__ __forceinline__ void cp16(uint32_t dst, const void* src, int sz) {
    asm volatile("cp.async.cg.shared.global [%0], [%1], 16, %2;"
                 :: "r"(dst), "l"(src), "r"(sz) : "memory");
}
#define CP_COMMIT() asm volatile("cp.async.commit_group;" ::: "memory")
#define CP_WAIT0()  asm volatile("cp.async.wait_group 0;" ::: "memory")
#define CP_WAIT1()  asm volatile("cp.async.wait_group 1;" ::: "memory")

// SMEM per buffer: AH@0, AL@10240, B@20480  (128 rows x 80B each).
// two buffers, stride 30720. Total 61440 B.
#define SMEM_BYTES 61440

// ====== GEMM core: 128x128 tile, 8 warps (2x4), 64x32 warp tile, cp.async x2 ======
// 2-product asymmetric: acc += Ahi*B + Alo*B.  chunk c at src + c*64B.
template <int NC, typename FE>
__device__ __forceinline__ void gemm_core(
    int tid, char* smem,
    const char* aHi, const char* aLo, int szA,
    const char* bSrc, FE epi)
{
    const int lane  = tid & 31;
    const int wid   = tid >> 5;
    const int warpM = wid >> 2;
    const int warpN = wid & 3;
    uint32_t sb = smem_u32(smem);
    const int lr = tid >> 1;
    uint32_t dstBase = sb + (uint32_t)(lr * 80 + (tid & 1) * 32);

    float acc[4][4][4];
    #pragma unroll
    for (int i = 0; i < 4; i++)
        #pragma unroll
        for (int t = 0; t < 4; t++)
            #pragma unroll
            for (int r = 0; r < 4; r++) acc[i][t][r] = 0.f;

    auto issue = [&](int c, int buf) {
        uint32_t d = dstBase + (uint32_t)buf * 30720u;
        const char* pAh = aHi + (size_t)c * 64;
        const char* pAl = aLo + (size_t)c * 64;
        const char* pB  = bSrc + (size_t)c * 64;
        cp16(d,              pAh,      szA); cp16(d + 16,         pAh + 16, szA);
        cp16(d + 10240,      pAl,      szA); cp16(d + 10240 + 16, pAl + 16, szA);
        cp16(d + 20480,      pB,       16);  cp16(d + 20480 + 16, pB + 16,  16);
    };

    issue(0, 0);
    CP_COMMIT();

    const uint32_t arow  = (uint32_t)((warpM * 64 + (lane & 15)) * 80);
    const uint32_t brow  = (uint32_t)((warpN * 32 + (lane & 7)) * 80);
    const uint32_t akoff = (uint32_t)(((lane >> 4) & 1) * 16);
    const uint32_t bkoff = (uint32_t)(((lane >> 3) & 1) * 16);

    #pragma unroll 1
    for (int c = 0; c < NC; c++) {
        if (c + 1 < NC) { issue(c + 1, (c + 1) & 1); CP_COMMIT(); CP_WAIT1(); }
        else            { CP_WAIT0(); }
        __syncthreads();
        uint32_t bufb = sb + (uint32_t)(c & 1) * 30720u;
        #pragma unroll
        for (int s = 0; s < 2; s++) {
            uint32_t ak = bufb + arow + (uint32_t)(s * 32) + akoff;
            uint32_t bk = bufb + 20480u + brow + (uint32_t)(s * 32) + bkoff;
            uint32_t ah[4][4], al[4][4], bf[4][2];
            #pragma unroll
            for (int i = 0; i < 4; i++) {
                ldsm_x4(ah[i], ak          + (uint32_t)(i * 16 * 80));
                ldsm_x4(al[i], ak + 10240u + (uint32_t)(i * 16 * 80));
            }
            #pragma unroll
            for (int t = 0; t < 4; t++)
                ldsm_x2(bf[t], bk + (uint32_t)(t * 8 * 80));
            #pragma unroll
            for (int i = 0; i < 4; i++)
                #pragma unroll
                for (int t = 0; t < 4; t++) mma16816(acc[i][t], ah[i], bf[t]);
            #pragma unroll
            for (int i = 0; i < 4; i++)
                #pragma unroll
                for (int t = 0; t < 4; t++) mma16816(acc[i][t], al[i], bf[t]);
        }
        __syncthreads();
    }
    epi(acc, warpM, warpN, lane);
}

// ---------------- operand pre-conversion ----------------
__global__ void split2_kernel(const float* __restrict__ in, uint32_t* __restrict__ hi,
                              uint32_t* __restrict__ lo, int n2)
{
    int i = blockIdx.x * blockDim.x + threadIdx.x;
    if (i < n2) {
        float2 v = ((const float2*)in)[i];
        uint32_t h, l;
        pack2_hilo(v.x, v.y, h, l);
        hi[i] = h;
        lo[i] = l;
    }
}
__global__ void split1_kernel(const float* __restrict__ in, uint32_t* __restrict__ dst, int n2)
{
    int i = blockIdx.x * blockDim.x + threadIdx.x;
    if (i < n2) {
        float2 v = ((const float2*)in)[i];
        dst[i] = pack2_single(v.x, v.y);
    }
}

// ---------------- routing ----------------
__global__ void zero_counts_kernel() {
    if (threadIdx.x < Ee) d_counts[threadIdx.x] = 0;
}

__global__ void router_kernel(const float* __restrict__ x, const float* __restrict__ gw) {
    int warp = threadIdx.x >> 5;
    int lane = threadIdx.x & 31;
    int t = blockIdx.x * 4 + warp;
    if (t >= T_TOK) return;
    const float* xr = x + (size_t)t * Dd;
    float logits[Ee];
    #pragma unroll 1
    for (int e = 0; e < Ee; e++) {
        const float* w = gw + (size_t)e * Dd;
        float p = 0.0f;
        for (int d = lane; d < Dd; d += 32) p += xr[d] * w[d];
        #pragma unroll
        for (int o = 16; o; o >>= 1) p += __shfl_down_sync(0xffffffffu, p, o);
        if (lane == 0) logits[e] = p;
    }
    if (lane == 0) {
        int i0 = 0; float v0 = logits[0];
        #pragma unroll
        for (int e = 1; e < Ee; e++) if (logits[e] > v0) { v0 = logits[e]; i0 = e; }
        int i1 = -1; float v1 = -3.0e38f;
        #pragma unroll
        for (int e = 0; e < Ee; e++) if (e != i0 && logits[e] > v1) { v1 = logits[e]; i1 = e; }
        float ex = expf(v1 - v0);
        float w0 = 1.0f / (1.0f + ex);
        float w1 = ex / (1.0f + ex);
        d_top_idx[2 * t]     = i0;
        d_top_idx[2 * t + 1] = i1;
        d_top_w[2 * t]       = w0;
        d_top_w[2 * t + 1]   = w1;
        atomicAdd(&d_counts[i0], 1);
        atomicAdd(&d_counts[i1], 1);
    }
}

__global__ void scan_kernel() {
    int o = 0;
    for (int e = 0; e < Ee; e++) { d_offsets[e] = o; d_cursor[e] = o; o += d_counts[e]; }
    d_offsets[Ee] = o;
}

__global__ void scatter_kernel() {
    int s = blockIdx.x * blockDim.x + threadIdx.x;
    if (s < T_TOK * TOPK) {
        int e = d_top_idx[s];
        int p = atomicAdd(&d_cursor[e], 1);
        d_perm[p] = s;
    }
}

// ================= GEMM kernels =================

// shared GEMM1: g[:, c0:c0+64] = silu(x@sfc1^T) * (x@sfc2^T)  (dual-B, interleaved rows)
__global__ void __launch_bounds__(256) shared1_mm()
{
    extern __shared__ char smem[];
    int tid = threadIdx.x;
    int row0 = blockIdx.y * 128;
    int c0g  = blockIdx.x * 64;
    int lr = tid >> 1, hb = (tid & 1) * 32;

    const char* aHi = (const char*)xs_hi + (size_t)(row0 + lr) * (Dd * 2) + hb;
    const char* aLo = (const char*)xs_lo + (size_t)(row0 + lr) * (Dd * 2) + hb;
    int q = lr >> 3, nn = lr & 7;
    size_t brow = (size_t)(c0g + (q >> 1) * 8 + nn) * (Dd * 2) + hb;
    const char* bSrc = (const char*)((q & 1) ? s2s : s1s) + brow;

    auto epi = [=](float acc[4][4][4], int warpM, int warpN, int lane) {
        int gid = lane >> 2, tig = lane & 3;
        #pragma unroll
        for (int i = 0; i < 4; i++) {
            int m = row0 + warpM * 64 + i * 16 + gid;
            #pragma unroll
            for (int j = 0; j < 2; j++) {
                int col = c0g + (warpN * 2 + j) * 8 + tig * 2;
                uint32_t h, l;
                size_t idx0 = (size_t)m * (Ss / 2) + (col >> 1);
                pack2_hilo(silu_f(acc[i][2*j][0]) * acc[i][2*j+1][0],
                           silu_f(acc[i][2*j][1]) * acc[i][2*j+1][1], h, l);
                g_hi[idx0] = h; g_lo[idx0] = l;
                size_t idx1 = (size_t)(m + 8) * (Ss / 2) + (col >> 1);
                pack2_hilo(silu_f(acc[i][2*j][2]) * acc[i][2*j+1][2],
                           silu_f(acc[i][2*j][3]) * acc[i][2*j+1][3], h, l);
                g_hi[idx1] = h; g_lo[idx1] = l;
            }
        }
    };
    gemm_core<Dd / 32>(tid, smem, aHi, aLo, 16, bSrc, epi);
}

// shared GEMM2: out = g @ sfc3^T  (K = S)
__global__ void __launch_bounds__(256) shared2_mm(float* __restrict__ out)
{
    extern __shared__ char smem[];
    int tid = threadIdx.x;
    int row0 = blockIdx.y * 128;
    int col0 = blockIdx.x * 128;
    int lr = tid >> 1, hb = (tid & 1) * 32;

    const char* aHi = (const char*)g_hi + (size_t)(row0 + lr) * (Ss * 2) + hb;
    const char* aLo = (const char*)g_lo + (size_t)(row0 + lr) * (Ss * 2) + hb;
    const char* bSrc = (const char*)s3s + (size_t)(col0 + lr) * (Ss * 2) + hb;

    auto epi = [=](float acc[4][4][4], int warpM, int warpN, int lane) {
        int gid = lane >> 2, tig = lane & 3;
        #pragma unroll
        for (int i = 0; i < 4; i++) {
            int m = row0 + warpM * 64 + i * 16 + gid;
            #pragma unroll
            for (int t = 0; t < 4; t++) {
                int col = col0 + warpN * 32 + t * 8 + tig * 2;
                *(float2*)(out + (size_t)m * Dd + col)       = make_float2(acc[i][t][0], acc[i][t][1]);
                *(float2*)(out + (size_t)(m + 8) * Dd + col) = make_float2(acc[i][t][2], acc[i][t][3]);
            }
        }
    };
    gemm_core<Ss / 32>(tid, smem, aHi, aLo, 16, bSrc, epi);
}

// MoE GEMM1: h[p] = silu(x[gather] @ w1[e]^T)
__global__ void __launch_bounds__(256) moe1_mm()
{
    int e = blockIdx.z;
    int Ms = d_offsets[e], Me = d_offsets[e + 1];
    int M = Me - Ms;
    int m0 = blockIdx.y * 128;
    if (m0 >= M) return;

    extern __shared__ char smem[];
    int tid = threadIdx.x;
    int col0 = blockIdx.x * 128;
    int lr = tid >> 1, hb = (tid & 1) * 32;

    int mrow = m0 + lr;
    bool okA = (mrow < M);
    int tok = okA ? (d_perm[Ms + mrow] >> 1) : 0;
    const char* aHi = (const char*)xs_hi + (size_t)tok * (Dd * 2) + hb;
    const char* aLo = (const char*)xs_lo + (size_t)tok * (Dd * 2) + hb;
    const char* bSrc = (const char*)w1s + ((size_t)e * Hh + col0 + lr) * (Dd * 2) + hb;

    auto epi = [=](float acc[4][4][4], int warpM, int warpN, int lane) {
        int gid = lane >> 2, tig = lane & 3;
        #pragma unroll
        for (int i = 0; i < 4; i++) {
            int mb = m0 + warpM * 64 + i * 16 + gid;
            #pragma unroll
            for (int t = 0; t < 4; t++) {
                int col = col0 + warpN * 32 + t * 8 + tig * 2;
                uint32_t h, l;
                if (mb < M) {
                    size_t idx = (size_t)(Ms + mb) * (Hh / 2) + (col >> 1);
                    pack2_hilo(silu_f(acc[i][t][0]), silu_f(acc[i][t][1]), h, l);
                    h_hi[idx] = h; h_lo[idx] = l;
                }
                if (mb + 8 < M) {
                    size_t idx = (size_t)(Ms + mb + 8) * (Hh / 2) + (col >> 1);
                    pack2_hilo(silu_f(acc[i][t][2]), silu_f(acc[i][t][3]), h, l);
                    h_hi[idx] = h; h_lo[idx] = l;
                }
            }
        }
    };
    gemm_core<Dd / 32>(tid, smem, aHi, aLo, okA ? 16 : 0, bSrc, epi);
}

// MoE GEMM2: slot_out[slot] = wk * (h @ w2[e]^T)
__global__ void __launch_bounds__(256) moe2_mm()
{
    int e = blockIdx.z;
    int Ms = d_offsets[e], Me = d_offsets[e + 1];
    int M = Me - Ms;
    int m0 = blockIdx.y * 128;
    if (m0 >= M) return;

    extern __shared__ char smem[];
    int tid = threadIdx.x;
    int col0 = blockIdx.x * 128;
    int lr = tid >> 1, hb = (tid & 1) * 32;

    int mrow = m0 + lr;
    bool okA = (mrow < M);
    size_t arow = (size_t)(Ms + (okA ? mrow : 0)) * (Hh * 2) + hb;
    const char* aHi = (const char*)h_hi + arow;
    const char* aLo = (const char*)h_lo + arow;
    const char* bSrc = (const char*)w2s + ((size_t)e * Dd + col0 + lr) * (Hh * 2) + hb;

    auto epi = [=](float acc[4][4][4], int warpM, int warpN, int lane) {
        int gid = lane >> 2, tig = lane & 3;
        #pragma unroll
        for (int i = 0; i < 4; i++) {
            int mb = m0 + warpM * 64 + i * 16 + gid;
            #pragma unroll
            for (int t = 0; t < 4; t++) {
                int col = col0 + warpN * 32 + t * 8 + tig * 2;
                if (mb < M) {
                    int slot = d_perm[Ms + mb];
                    float wk = d_top_w[slot];
                    *(float2*)(slot_out + (size_t)slot * Dd + col) =
                        make_float2(wk * acc[i][t][0], wk * acc[i][t][1]);
                }
                if (mb + 8 < M) {
                    int slot = d_perm[Ms + mb + 8];
                    float wk = d_top_w[slot];
                    *(float2*)(slot_out + (size_t)slot * Dd + col) =
                        make_float2(wk * acc[i][t][2], wk * acc[i][t][3]);
                }
            }
        }
    };
    gemm_core<Hh / 32>(tid, smem, aHi, aLo, okA ? 16 : 0, bSrc, epi);
}

// out = shared (already in out) + slot0 + slot1
__global__ void combine_kernel(float* __restrict__ out)
{
    int i = blockIdx.x * blockDim.x + threadIdx.x;
    int e0 = i * 4;
    int t = e0 / Dd;
    int d = e0 - t * Dd;
    float4 o  = ((const float4*)out)[i];
    float4 s0 = *(const float4*)&slot_out[(size_t)(2 * t) * Dd + d];
    float4 s1 = *(const float4*)&slot_out[(size_t)(2 * t + 1) * Dd + d];
    o.x += s0.x + s1.x;
    o.y += s0.y + s1.y;
    o.z += s0.z + s1.z;
    o.w += s0.w + s1.w;
    ((float4*)out)[i] = o;
}

// ---------------- launch ----------------
extern "C" void kernel_launch(void* const* d_in, const int* in_sizes, int n_in,
                              void* d_out, int out_size)
{
    const float* x     = (const float*)d_in[0];
    const float* gatew = (const float*)d_in[1];
    const float* w1    = (const float*)d_in[2];
    const float* w2    = (const float*)d_in[3];
    const float* sfc1  = (const float*)d_in[4];
    const float* sfc2  = (const float*)d_in[5];
    const float* sfc3  = (const float*)d_in[6];
    float* out = (float*)d_out;

    cudaFuncSetAttribute(shared1_mm, cudaFuncAttributeMaxDynamicSharedMemorySize, SMEM_BYTES);
    cudaFuncSetAttribute(shared2_mm, cudaFuncAttributeMaxDynamicSharedMemorySize, SMEM_BYTES);
    cudaFuncSetAttribute(moe1_mm,    cudaFuncAttributeMaxDynamicSharedMemorySize, SMEM_BYTES);
    cudaFuncSetAttribute(moe2_mm,    cudaFuncAttributeMaxDynamicSharedMemorySize, SMEM_BYTES);

    uint32_t *p_xh, *p_xl, *p_w1, *p_w2, *p_s1, *p_s2, *p_s3;
    cudaGetSymbolAddress((void**)&p_xh, xs_hi); cudaGetSymbolAddress((void**)&p_xl, xs_lo);
    cudaGetSymbolAddress((void**)&p_w1, w1s);   cudaGetSymbolAddress((void**)&p_w2, w2s);
    cudaGetSymbolAddress((void**)&p_s1, s1s);   cudaGetSymbolAddress((void**)&p_s2, s2s);
    cudaGetSymbolAddress((void**)&p_s3, s3s);

    // routing path
    zero_counts_kernel<<<1, 32>>>();
    router_kernel<<<T_TOK / 4, 128>>>(x, gatew);
    scan_kernel<<<1, 1>>>();
    scatter_kernel<<<(T_TOK * TOPK + 255) / 256, 256>>>();

    // operand pre-conversion (A-side: fp16 hi/lo, B-side: single fp16)
    {
        int n2;
        n2 = T_TOK * Dd / 2;     split2_kernel<<<(n2 + 255) / 256, 256>>>(x,    p_xh, p_xl, n2);
        n2 = Ee * Hh * Dd / 2;   split1_kernel<<<(n2 + 255) / 256, 256>>>(w1,   p_w1, n2);
        n2 = Ee * Dd * Hh / 2;   split1_kernel<<<(n2 + 255) / 256, 256>>>(w2,   p_w2, n2);
        n2 = Ss * Dd / 2;        split1_kernel<<<(n2 + 255) / 256, 256>>>(sfc1, p_s1, n2);
        n2 = Ss * Dd / 2;        split1_kernel<<<(n2 + 255) / 256, 256>>>(sfc2, p_s2, n2);
        n2 = Dd * Ss / 2;        split1_kernel<<<(n2 + 255) / 256, 256>>>(sfc3, p_s3, n2);
    }

    // shared expert
    shared1_mm<<<dim3(Ss / 64, T_TOK / 128), 256, SMEM_BYTES>>>();
    shared2_mm<<<dim3(Dd / 128, T_TOK / 128), 256, SMEM_BYTES>>>(out);

    // sparse MoE (grouped by expert)
    moe1_mm<<<dim3(Hh / 128, (T_TOK * TOPK) / 128, Ee), 256, SMEM_BYTES>>>();
    moe2_mm<<<dim3(Dd / 128, (T_TOK * TOPK) / 128, Ee), 256, SMEM_BYTES>>>();

    // final combine
    combine_kernel<<<(T_TOK * Dd / 4) / 256, 256>>>(out);
}

// round 13
// speedup vs baseline: 4.0322x; 1.4125x over previous
#include <cuda_runtime.h>
#include <cuda_fp16.h>
#include <math.h>
#include <stdint.h>

// Problem constants
#define T_TOK 4096      // B*L tokens
#define Dd    1024      // model dim
#define Hh    512       // expert hidden
#define Ee    16        // num experts
#define Ss    2048      // shared expert hidden
#define TOPK  2

// ---------------- device scratch (no allocations allowed) ----------------
// all GEMM operands single fp16 (uint32 = half2)
__device__ uint32_t xs16[(size_t)T_TOK * Dd / 2];
__device__ uint32_t w1s[(size_t)Ee * Hh * Dd / 2];
__device__ uint32_t w2s[(size_t)Ee * Dd * Hh / 2];
__device__ uint32_t s1s[(size_t)Ss * Dd / 2];
__device__ uint32_t s2s[(size_t)Ss * Dd / 2];
__device__ uint32_t s3s[(size_t)Dd * Ss / 2];
__device__ uint32_t g16[(size_t)T_TOK * Ss / 2];
__device__ uint32_t h16[(size_t)T_TOK * TOPK * Hh / 2];
__device__ float slot_out[(size_t)T_TOK * TOPK * Dd];
__device__ int   d_top_idx[T_TOK * TOPK];
__device__ float d_top_w[T_TOK * TOPK];
__device__ int   d_counts[Ee];
__device__ int   d_offsets[Ee + 1];
__device__ int   d_cursor[Ee];
__device__ int   d_perm[T_TOK * TOPK];

__device__ __forceinline__ float silu_f(float v) { return v / (1.0f + expf(-v)); }

__device__ __forceinline__ uint32_t smem_u32(const void* p) {
    uint32_t a;
    asm("{ .reg .u64 t; cvta.to.shared.u64 t, %1; cvt.u32.u64 %0, t; }" : "=r"(a) : "l"(p));
    return a;
}
__device__ __forceinline__ uint32_t pack2_single(float a, float b) {
    __half2 h = __floats2half2_rn(a, b);
    return *(uint32_t*)&h;
}

__device__ __forceinline__ void ldsm_x4(uint32_t* r, uint32_t addr) {
    asm volatile("ldmatrix.sync.aligned.m8n8.x4.shared.b16 {%0,%1,%2,%3}, [%4];"
        : "=r"(r[0]), "=r"(r[1]), "=r"(r[2]), "=r"(r[3]) : "r"(addr));
}
__device__ __forceinline__ void ldsm_x2(uint32_t* r, uint32_t addr) {
    asm volatile("ldmatrix.sync.aligned.m8n8.x2.shared.b16 {%0,%1}, [%2];"
        : "=r"(r[0]), "=r"(r[1]) : "r"(addr));
}
__device__ __forceinline__ void mma16816(float* c, const uint32_t* a, const uint32_t* b) {
    asm volatile(
        "mma.sync.aligned.m16n8k16.row.col.f32.f16.f16.f32 "
        "{%0,%1,%2,%3}, {%4,%5,%6,%7}, {%8,%9}, {%0,%1,%2,%3};"
        : "+f"(c[0]), "+f"(c[1]), "+f"(c[2]), "+f"(c[3])
        : "r"(a[0]), "r"(a[1]), "r"(a[2]), "r"(a[3]), "r"(b[0]), "r"(b[1]));
}

__device__ __forceinline__ void cp16(uint32_t dst, const void* src, int sz) {
    asm volatile("cp.async.cg.shared.global [%0], [%1], 16, %2;"
                 :: "r"(dst), "l"(src), "r"(sz) : "memory");
}
#define CP_COMMIT() asm volatile("cp.async.commit_group;" ::: "memory")
#define CP_WAIT0()  asm volatile("cp.async.wait_group 0;" ::: "memory")
#define CP_WAIT1()  asm volatile("cp.async.wait_group 1;" ::: "memory")

// SMEM per buffer: A@0, B@10240  (128 rows x 80B each). two buffers, stride 20480.
#define SMEM_BYTES 40960

// ====== GEMM core: 128x128 tile, 8 warps (2x4), 64x32 warp tile, cp.async x2 ======
// single-product fp16: acc += A*B.  chunk c at src + c*64B.
template <int NC, typename FE>
__device__ __forceinline__ void gemm_core(
    int tid, char* smem,
    const char* aSrc, int szA,
    const char* bSrc, FE epi)
{
    const int lane  = tid & 31;
    const int wid   = tid >> 5;
    const int warpM = wid >> 2;
    const int warpN = wid & 3;
    uint32_t sb = smem_u32(smem);
    const int lr = tid >> 1;
    uint32_t dstBase = sb + (uint32_t)(lr * 80 + (tid & 1) * 32);

    float acc[4][4][4];
    #pragma unroll
    for (int i = 0; i < 4; i++)
        #pragma unroll
        for (int t = 0; t < 4; t++)
            #pragma unroll
            for (int r = 0; r < 4; r++) acc[i][t][r] = 0.f;

    auto issue = [&](int c, int buf) {
        uint32_t d = dstBase + (uint32_t)buf * 20480u;
        const char* pA = aSrc + (size_t)c * 64;
        const char* pB = bSrc + (size_t)c * 64;
        cp16(d,          pA,      szA); cp16(d + 16,         pA + 16, szA);
        cp16(d + 10240,  pB,      16);  cp16(d + 10240 + 16, pB + 16, 16);
    };

    issue(0, 0);
    CP_COMMIT();

    const uint32_t arow  = (uint32_t)((warpM * 64 + (lane & 15)) * 80);
    const uint32_t brow  = (uint32_t)((warpN * 32 + (lane & 7)) * 80);
    const uint32_t akoff = (uint32_t)(((lane >> 4) & 1) * 16);
    const uint32_t bkoff = (uint32_t)(((lane >> 3) & 1) * 16);

    #pragma unroll 1
    for (int c = 0; c < NC; c++) {
        if (c + 1 < NC) { issue(c + 1, (c + 1) & 1); CP_COMMIT(); CP_WAIT1(); }
        else            { CP_WAIT0(); }
        __syncthreads();
        uint32_t bufb = sb + (uint32_t)(c & 1) * 20480u;
        #pragma unroll
        for (int s = 0; s < 2; s++) {
            uint32_t ak = bufb + arow + (uint32_t)(s * 32) + akoff;
            uint32_t bk = bufb + 10240u + brow + (uint32_t)(s * 32) + bkoff;
            uint32_t af[4][4], bf[4][2];
            #pragma unroll
            for (int i = 0; i < 4; i++)
                ldsm_x4(af[i], ak + (uint32_t)(i * 16 * 80));
            #pragma unroll
            for (int t = 0; t < 4; t++)
                ldsm_x2(bf[t], bk + (uint32_t)(t * 8 * 80));
            #pragma unroll
            for (int i = 0; i < 4; i++)
                #pragma unroll
                for (int t = 0; t < 4; t++) mma16816(acc[i][t], af[i], bf[t]);
        }
        __syncthreads();
    }
    epi(acc, warpM, warpN, lane);
}

// ---------------- operand pre-conversion ----------------
__global__ void split1_kernel(const float* __restrict__ in, uint32_t* __restrict__ dst, int n2)
{
    int i = blockIdx.x * blockDim.x + threadIdx.x;
    if (i < n2) {
        float2 v = ((const float2*)in)[i];
        dst[i] = pack2_single(v.x, v.y);
    }
}

// ---------------- routing ----------------
__global__ void zero_counts_kernel() {
    if (threadIdx.x < Ee) d_counts[threadIdx.x] = 0;
}

__global__ void router_kernel(const float* __restrict__ x, const float* __restrict__ gw) {
    int warp = threadIdx.x >> 5;
    int lane = threadIdx.x & 31;
    int t = blockIdx.x * 4 + warp;
    if (t >= T_TOK) return;
    const float* xr = x + (size_t)t * Dd;
    float logits[Ee];
    #pragma unroll 1
    for (int e = 0; e < Ee; e++) {
        const float* w = gw + (size_t)e * Dd;
        float p = 0.0f;
        for (int d = lane; d < Dd; d += 32) p += xr[d] * w[d];
        #pragma unroll
        for (int o = 16; o; o >>= 1) p += __shfl_down_sync(0xffffffffu, p, o);
        if (lane == 0) logits[e] = p;
    }
    if (lane == 0) {
        int i0 = 0; float v0 = logits[0];
        #pragma unroll
        for (int e = 1; e < Ee; e++) if (logits[e] > v0) { v0 = logits[e]; i0 = e; }
        int i1 = -1; float v1 = -3.0e38f;
        #pragma unroll
        for (int e = 0; e < Ee; e++) if (e != i0 && logits[e] > v1) { v1 = logits[e]; i1 = e; }
        float ex = expf(v1 - v0);
        float w0 = 1.0f / (1.0f + ex);
        float w1 = ex / (1.0f + ex);
        d_top_idx[2 * t]     = i0;
        d_top_idx[2 * t + 1] = i1;
        d_top_w[2 * t]       = w0;
        d_top_w[2 * t + 1]   = w1;
        atomicAdd(&d_counts[i0], 1);
        atomicAdd(&d_counts[i1], 1);
    }
}

__global__ void scan_kernel() {
    int o = 0;
    for (int e = 0; e < Ee; e++) { d_offsets[e] = o; d_cursor[e] = o; o += d_counts[e]; }
    d_offsets[Ee] = o;
}

__global__ void scatter_kernel() {
    int s = blockIdx.x * blockDim.x + threadIdx.x;
    if (s < T_TOK * TOPK) {
        int e = d_top_idx[s];
        int p = atomicAdd(&d_cursor[e], 1);
        d_perm[p] = s;
    }
}

// ================= GEMM kernels =================

// shared GEMM1: g[:, c0:c0+64] = silu(x@sfc1^T) * (x@sfc2^T)  (dual-B, interleaved rows)
__global__ void __launch_bounds__(256) shared1_mm()
{
    extern __shared__ char smem[];
    int tid = threadIdx.x;
    int row0 = blockIdx.y * 128;
    int c0g  = blockIdx.x * 64;
    int lr = tid >> 1, hb = (tid & 1) * 32;

    const char* aSrc = (const char*)xs16 + (size_t)(row0 + lr) * (Dd * 2) + hb;
    int q = lr >> 3, nn = lr & 7;
    size_t brow = (size_t)(c0g + (q >> 1) * 8 + nn) * (Dd * 2) + hb;
    const char* bSrc = (const char*)((q & 1) ? s2s : s1s) + brow;

    auto epi = [=](float acc[4][4][4], int warpM, int warpN, int lane) {
        int gid = lane >> 2, tig = lane & 3;
        #pragma unroll
        for (int i = 0; i < 4; i++) {
            int m = row0 + warpM * 64 + i * 16 + gid;
            #pragma unroll
            for (int j = 0; j < 2; j++) {
                int col = c0g + (warpN * 2 + j) * 8 + tig * 2;
                size_t idx0 = (size_t)m * (Ss / 2) + (col >> 1);
                g16[idx0] = pack2_single(silu_f(acc[i][2*j][0]) * acc[i][2*j+1][0],
                                         silu_f(acc[i][2*j][1]) * acc[i][2*j+1][1]);
                size_t idx1 = (size_t)(m + 8) * (Ss / 2) + (col >> 1);
                g16[idx1] = pack2_single(silu_f(acc[i][2*j][2]) * acc[i][2*j+1][2],
                                         silu_f(acc[i][2*j][3]) * acc[i][2*j+1][3]);
            }
        }
    };
    gemm_core<Dd / 32>(tid, smem, aSrc, 16, bSrc, epi);
}

// shared GEMM2: out = g @ sfc3^T  (K = S)
__global__ void __launch_bounds__(256) shared2_mm(float* __restrict__ out)
{
    extern __shared__ char smem[];
    int tid = threadIdx.x;
    int row0 = blockIdx.y * 128;
    int col0 = blockIdx.x * 128;
    int lr = tid >> 1, hb = (tid & 1) * 32;

    const char* aSrc = (const char*)g16 + (size_t)(row0 + lr) * (Ss * 2) + hb;
    const char* bSrc = (const char*)s3s + (size_t)(col0 + lr) * (Ss * 2) + hb;

    auto epi = [=](float acc[4][4][4], int warpM, int warpN, int lane) {
        int gid = lane >> 2, tig = lane & 3;
        #pragma unroll
        for (int i = 0; i < 4; i++) {
            int m = row0 + warpM * 64 + i * 16 + gid;
            #pragma unroll
            for (int t = 0; t < 4; t++) {
                int col = col0 + warpN * 32 + t * 8 + tig * 2;
                *(float2*)(out + (size_t)m * Dd + col)       = make_float2(acc[i][t][0], acc[i][t][1]);
                *(float2*)(out + (size_t)(m + 8) * Dd + col) = make_float2(acc[i][t][2], acc[i][t][3]);
            }
        }
    };
    gemm_core<Ss / 32>(tid, smem, aSrc, 16, bSrc, epi);
}

// MoE GEMM1: h[p] = silu(x[gather] @ w1[e]^T)
__global__ void __launch_bounds__(256) moe1_mm()
{
    int e = blockIdx.z;
    int Ms = d_offsets[e], Me = d_offsets[e + 1];
    int M = Me - Ms;
    int m0 = blockIdx.y * 128;
    if (m0 >= M) return;

    extern __shared__ char smem[];
    int tid = threadIdx.x;
    int col0 = blockIdx.x * 128;
    int lr = tid >> 1, hb = (tid & 1) * 32;

    int mrow = m0 + lr;
    bool okA = (mrow < M);
    int tok = okA ? (d_perm[Ms + mrow] >> 1) : 0;
    const char* aSrc = (const char*)xs16 + (size_t)tok * (Dd * 2) + hb;
    const char* bSrc = (const char*)w1s + ((size_t)e * Hh + col0 + lr) * (Dd * 2) + hb;

    auto epi = [=](float acc[4][4][4], int warpM, int warpN, int lane) {
        int gid = lane >> 2, tig = lane & 3;
        #pragma unroll
        for (int i = 0; i < 4; i++) {
            int mb = m0 + warpM * 64 + i * 16 + gid;
            #pragma unroll
            for (int t = 0; t < 4; t++) {
                int col = col0 + warpN * 32 + t * 8 + tig * 2;
                if (mb < M) {
                    size_t idx = (size_t)(Ms + mb) * (Hh / 2) + (col >> 1);
                    h16[idx] = pack2_single(silu_f(acc[i][t][0]), silu_f(acc[i][t][1]));
                }
                if (mb + 8 < M) {
                    size_t idx = (size_t)(Ms + mb + 8) * (Hh / 2) + (col >> 1);
                    h16[idx] = pack2_single(silu_f(acc[i][t][2]), silu_f(acc[i][t][3]));
                }
            }
        }
    };
    gemm_core<Dd / 32>(tid, smem, aSrc, okA ? 16 : 0, bSrc, epi);
}

// MoE GEMM2: slot_out[slot] = wk * (h @ w2[e]^T)
__global__ void __launch_bounds__(256) moe2_mm()
{
    int e = blockIdx.z;
    int Ms = d_offsets[e], Me = d_offsets[e + 1];
    int M = Me - Ms;
    int m0 = blockIdx.y * 128;
    if (m0 >= M) return;

    extern __shared__ char smem[];
    int tid = threadIdx.x;
    int col0 = blockIdx.x * 128;
    int lr = tid >> 1, hb = (tid & 1) * 32;

    int mrow = m0 + lr;
    bool okA = (mrow < M);
    const char* aSrc = (const char*)h16 + (size_t)(Ms + (okA ? mrow : 0)) * (Hh * 2) + hb;
    const char* bSrc = (const char*)w2s + ((size_t)e * Dd + col0 + lr) * (Hh * 2) + hb;

    auto epi = [=](float acc[4][4][4], int warpM, int warpN, int lane) {
        int gid = lane >> 2, tig = lane & 3;
        #pragma unroll
        for (int i = 0; i < 4; i++) {
            int mb = m0 + warpM * 64 + i * 16 + gid;
            #pragma unroll
            for (int t = 0; t < 4; t++) {
                int col = col0 + warpN * 32 + t * 8 + tig * 2;
                if (mb < M) {
                    int slot = d_perm[Ms + mb];
                    float wk = d_top_w[slot];
                    *(float2*)(slot_out + (size_t)slot * Dd + col) =
                        make_float2(wk * acc[i][t][0], wk * acc[i][t][1]);
                }
                if (mb + 8 < M) {
                    int slot = d_perm[Ms + mb + 8];
                    float wk = d_top_w[slot];
                    *(float2*)(slot_out + (size_t)slot * Dd + col) =
                        make_float2(wk * acc[i][t][2], wk * acc[i][t][3]);
                }
            }
        }
    };
    gemm_core<Hh / 32>(tid, smem, aSrc, okA ? 16 : 0, bSrc, epi);
}

// out = shared (already in out) + slot0 + slot1
__global__ void combine_kernel(float* __restrict__ out)
{
    int i = blockIdx.x * blockDim.x + threadIdx.x;
    int e0 = i * 4;
    int t = e0 / Dd;
    int d = e0 - t * Dd;
    float4 o  = ((const float4*)out)[i];
    float4 s0 = *(const float4*)&slot_out[(size_t)(2 * t) * Dd + d];
    float4 s1 = *(const float4*)&slot_out[(size_t)(2 * t + 1) * Dd + d];
    o.x += s0.x + s1.x;
    o.y += s0.y + s1.y;
    o.z += s0.z + s1.z;
    o.w += s0.w + s1.w;
    ((float4*)out)[i] = o;
}

// ---------------- launch ----------------
extern "C" void kernel_launch(void* const* d_in, const int* in_sizes, int n_in,
                              void* d_out, int out_size)
{
    const float* x     = (const float*)d_in[0];
    const float* gatew = (const float*)d_in[1];
    const float* w1    = (const float*)d_in[2];
    const float* w2    = (const float*)d_in[3];
    const float* sfc1  = (const float*)d_in[4];
    const float* sfc2  = (const float*)d_in[5];
    const float* sfc3  = (const float*)d_in[6];
    float* out = (float*)d_out;

    cudaFuncSetAttribute(shared1_mm, cudaFuncAttributeMaxDynamicSharedMemorySize, SMEM_BYTES);
    cudaFuncSetAttribute(shared2_mm, cudaFuncAttributeMaxDynamicSharedMemorySize, SMEM_BYTES);
    cudaFuncSetAttribute(moe1_mm,    cudaFuncAttributeMaxDynamicSharedMemorySize, SMEM_BYTES);
    cudaFuncSetAttribute(moe2_mm,    cudaFuncAttributeMaxDynamicSharedMemorySize, SMEM_BYTES);

    uint32_t *p_x, *p_w1, *p_w2, *p_s1, *p_s2, *p_s3;
    cudaGetSymbolAddress((void**)&p_x,  xs16);
    cudaGetSymbolAddress((void**)&p_w1, w1s);   cudaGetSymbolAddress((void**)&p_w2, w2s);
    cudaGetSymbolAddress((void**)&p_s1, s1s);   cudaGetSymbolAddress((void**)&p_s2, s2s);
    cudaGetSymbolAddress((void**)&p_s3, s3s);

    // routing path
    zero_counts_kernel<<<1, 32>>>();
    router_kernel<<<T_TOK / 4, 128>>>(x, gatew);
    scan_kernel<<<1, 1>>>();
    scatter_kernel<<<(T_TOK * TOPK + 255) / 256, 256>>>();

    // operand pre-conversion (all fp16)
    {
        int n2;
        n2 = T_TOK * Dd / 2;     split1_kernel<<<(n2 + 255) / 256, 256>>>(x,    p_x,  n2);
        n2 = Ee * Hh * Dd / 2;   split1_kernel<<<(n2 + 255) / 256, 256>>>(w1,   p_w1, n2);
        n2 = Ee * Dd * Hh / 2;   split1_kernel<<<(n2 + 255) / 256, 256>>>(w2,   p_w2, n2);
        n2 = Ss * Dd / 2;        split1_kernel<<<(n2 + 255) / 256, 256>>>(sfc1, p_s1, n2);
        n2 = Ss * Dd / 2;        split1_kernel<<<(n2 + 255) / 256, 256>>>(sfc2, p_s2, n2);
        n2 = Dd * Ss / 2;        split1_kernel<<<(n2 + 255) / 256, 256>>>(sfc3, p_s3, n2);
    }

    // shared expert
    shared1_mm<<<dim3(Ss / 64, T_TOK / 128), 256, SMEM_BYTES>>>();
    shared2_mm<<<dim3(Dd / 128, T_TOK / 128), 256, SMEM_BYTES>>>(out);

    // sparse MoE (grouped by expert)
    moe1_mm<<<dim3(Hh / 128, (T_TOK * TOPK) / 128, Ee), 256, SMEM_BYTES>>>();
    moe2_mm<<<dim3(Dd / 128, (T_TOK * TOPK) / 128, Ee), 256, SMEM_BYTES>>>();

    // final combine
    combine_kernel<<<(T_TOK * Dd / 4) / 256, 256>>>(out);
}

// round 15
// speedup vs baseline: 4.7941x; 1.1889x over previous
#include <cuda_runtime.h>
#include <cuda_fp16.h>
#include <math.h>
#include <stdint.h>

// Problem constants
#define T_TOK 4096      // B*L tokens
#define Dd    1024      // model dim
#define Hh    512       // expert hidden
#define Ee    16        // num experts
#define Ss    2048      // shared expert hidden
#define TOPK  2

// ---------------- device scratch (no allocations allowed) ----------------
__device__ uint32_t xs16[(size_t)T_TOK * Dd / 2];
__device__ uint32_t w1s[(size_t)Ee * Hh * Dd / 2];
__device__ uint32_t w2s[(size_t)Ee * Dd * Hh / 2];
__device__ uint32_t s1s[(size_t)Ss * Dd / 2];
__device__ uint32_t s2s[(size_t)Ss * Dd / 2];
__device__ uint32_t s3s[(size_t)Dd * Ss / 2];
__device__ uint32_t g16[(size_t)T_TOK * Ss / 2];
__device__ uint32_t h16[(size_t)T_TOK * TOPK * Hh / 2];
__device__ int   d_top_idx[T_TOK * TOPK];
__device__ float d_top_w[T_TOK * TOPK];
__device__ int   d_counts[Ee];
__device__ int   d_offsets[Ee + 1];
__device__ int   d_cursor[Ee];
__device__ int   d_perm[T_TOK * TOPK];

__device__ __forceinline__ float silu_f(float v) { return v / (1.0f + expf(-v)); }

__device__ __forceinline__ uint32_t smem_u32(const void* p) {
    uint32_t a;
    asm("{ .reg .u64 t; cvta.to.shared.u64 t, %1; cvt.u32.u64 %0, t; }" : "=r"(a) : "l"(p));
    return a;
}
__device__ __forceinline__ uint32_t pack2_single(float a, float b) {
    __half2 h = __floats2half2_rn(a, b);
    return *(uint32_t*)&h;
}

__device__ __forceinline__ void ldsm_x4(uint32_t* r, uint32_t addr) {
    asm volatile("ldmatrix.sync.aligned.m8n8.x4.shared.b16 {%0,%1,%2,%3}, [%4];"
        : "=r"(r[0]), "=r"(r[1]), "=r"(r[2]), "=r"(r[3]) : "r"(addr));
}
__device__ __forceinline__ void ldsm_x2(uint32_t* r, uint32_t addr) {
    asm volatile("ldmatrix.sync.aligned.m8n8.x2.shared.b16 {%0,%1}, [%2];"
        : "=r"(r[0]), "=r"(r[1]) : "r"(addr));
}
__device__ __forceinline__ void mma16816(float* c, const uint32_t* a, const uint32_t* b) {
    asm volatile(
        "mma.sync.aligned.m16n8k16.row.col.f32.f16.f16.f32 "
        "{%0,%1,%2,%3}, {%4,%5,%6,%7}, {%8,%9}, {%0,%1,%2,%3};"
        : "+f"(c[0]), "+f"(c[1]), "+f"(c[2]), "+f"(c[3])
        : "r"(a[0]), "r"(a[1]), "r"(a[2]), "r"(a[3]), "r"(b[0]), "r"(b[1]));
}

__device__ __forceinline__ void cp16(uint32_t dst, const void* src, int sz) {
    asm volatile("cp.async.cg.shared.global [%0], [%1], 16, %2;"
                 :: "r"(dst), "l"(src), "r"(sz) : "memory");
}
#define CP_COMMIT() asm volatile("cp.async.commit_group;" ::: "memory")
#define CP_WAIT0()  asm volatile("cp.async.wait_group 0;" ::: "memory")
#define CP_WAIT1()  asm volatile("cp.async.wait_group 1;" ::: "memory")

// SMEM per stage: A@0, B@10240 (128 rows x 80B each). 3 stages, stride 20480.
#define STAGE_BYTES 20480
#define SMEM_BYTES  61440

// ====== GEMM core: 128x128 tile, 8 warps (2x4), 64x32 warp tile, cp.async x3 ======
template <int NC, typename FE>
__device__ __forceinline__ void gemm_core(
    int tid, char* smem,
    const char* aSrc, int szA,
    const char* bSrc, FE epi)
{
    const int lane  = tid & 31;
    const int wid   = tid >> 5;
    const int warpM = wid >> 2;
    const int warpN = wid & 3;
    uint32_t sb = smem_u32(smem);
    const int lr = tid >> 1;
    uint32_t dstBase = sb + (uint32_t)(lr * 80 + (tid & 1) * 32);

    float acc[4][4][4];
    #pragma unroll
    for (int i = 0; i < 4; i++)
        #pragma unroll
        for (int t = 0; t < 4; t++)
            #pragma unroll
            for (int r = 0; r < 4; r++) acc[i][t][r] = 0.f;

    auto issue = [&](int c) {
        uint32_t d = dstBase + (uint32_t)(c % 3) * (uint32_t)STAGE_BYTES;
        const char* pA = aSrc + (size_t)c * 64;
        const char* pB = bSrc + (size_t)c * 64;
        cp16(d,          pA,      szA); cp16(d + 16,         pA + 16, szA);
        cp16(d + 10240,  pB,      16);  cp16(d + 10240 + 16, pB + 16, 16);
    };

    issue(0); CP_COMMIT();
    if (NC > 1) { issue(1); CP_COMMIT(); }

    const uint32_t arow  = (uint32_t)((warpM * 64 + (lane & 15)) * 80);
    const uint32_t brow  = (uint32_t)((warpN * 32 + (lane & 7)) * 80);
    const uint32_t akoff = (uint32_t)(((lane >> 4) & 1) * 16);
    const uint32_t bkoff = (uint32_t)(((lane >> 3) & 1) * 16);

    #pragma unroll 1
    for (int c = 0; c < NC; c++) {
        if (c + 1 < NC) CP_WAIT1(); else CP_WAIT0();
        __syncthreads();
        uint32_t bufb = sb + (uint32_t)(c % 3) * (uint32_t)STAGE_BYTES;
        #pragma unroll
        for (int s = 0; s < 2; s++) {
            uint32_t ak = bufb + arow + (uint32_t)(s * 32) + akoff;
            uint32_t bk = bufb + 10240u + brow + (uint32_t)(s * 32) + bkoff;
            uint32_t af[4][4], bf[4][2];
            #pragma unroll
            for (int i = 0; i < 4; i++)
                ldsm_x4(af[i], ak + (uint32_t)(i * 16 * 80));
            #pragma unroll
            for (int t = 0; t < 4; t++)
                ldsm_x2(bf[t], bk + (uint32_t)(t * 8 * 80));
            #pragma unroll
            for (int i = 0; i < 4; i++)
                #pragma unroll
                for (int t = 0; t < 4; t++) mma16816(acc[i][t], af[i], bf[t]);
        }
        if (c + 2 < NC) { issue(c + 2); CP_COMMIT(); }
    }
    epi(acc, warpM, warpN, lane);
}

// ---------------- fused operand pre-conversion (+ counts zeroing) ----------------
#define N2_X   (T_TOK * Dd / 2)
#define N2_W1  (Ee * Hh * Dd / 2)
#define N2_W2  (Ee * Dd * Hh / 2)
#define N2_S1  (Ss * Dd / 2)
#define N2_S2  (Ss * Dd / 2)
#define N2_S3  (Dd * Ss / 2)
#define N2_TOT (N2_X + N2_W1 + N2_W2 + N2_S1 + N2_S2 + N2_S3)

__global__ void split_all_kernel(
    const float* __restrict__ x,  const float* __restrict__ w1,
    const float* __restrict__ w2, const float* __restrict__ sfc1,
    const float* __restrict__ sfc2, const float* __restrict__ sfc3)
{
    if (blockIdx.x == 0 && threadIdx.x < Ee) d_counts[threadIdx.x] = 0;
    int i = blockIdx.x * blockDim.x + threadIdx.x;
    if (i >= N2_TOT) return;
    const float* src;
    uint32_t* dst;
    int j = i;
    if (j < N2_X)                     { src = x;    dst = xs16; }
    else if ((j -= N2_X)  < N2_W1)    { src = w1;   dst = w1s; }
    else if ((j -= N2_W1) < N2_W2)    { src = w2;   dst = w2s; }
    else if ((j -= N2_W2) < N2_S1)    { src = sfc1; dst = s1s; }
    else if ((j -= N2_S1) < N2_S2)    { src = sfc2; dst = s2s; }
    else       { j -= N2_S2;            src = sfc3; dst = s3s; }
    float2 v = ((const float2*)src)[j];
    dst[j] = pack2_single(v.x, v.y);
}

// ---------------- routing ----------------
// one warp per token; x cached in registers, experts looped inner.
__global__ void router_kernel(const float* __restrict__ x, const float* __restrict__ gw) {
    int warp = threadIdx.x >> 5;
    int lane = threadIdx.x & 31;
    int t = blockIdx.x * 4 + warp;
    if (t >= T_TOK) return;
    const float* xr = x + (size_t)t * Dd;
    float xv[32];
    #pragma unroll
    for (int j = 0; j < 32; j++) xv[j] = xr[lane + 32 * j];
    float logits[Ee];
    #pragma unroll 1
    for (int e = 0; e < Ee; e++) {
        const float* w = gw + (size_t)e * Dd;
        float p = 0.0f;
        #pragma unroll
        for (int j = 0; j < 32; j++) p += xv[j] * w[lane + 32 * j];
        #pragma unroll
        for (int o = 16; o; o >>= 1) p += __shfl_down_sync(0xffffffffu, p, o);
        if (lane == 0) logits[e] = p;
    }
    if (lane == 0) {
        int i0 = 0; float v0 = logits[0];
        #pragma unroll
        for (int e = 1; e < Ee; e++) if (logits[e] > v0) { v0 = logits[e]; i0 = e; }
        int i1 = -1; float v1 = -3.0e38f;
        #pragma unroll
        for (int e = 0; e < Ee; e++) if (e != i0 && logits[e] > v1) { v1 = logits[e]; i1 = e; }
        float ex = expf(v1 - v0);
        float w0 = 1.0f / (1.0f + ex);
        float w1 = ex / (1.0f + ex);
        d_top_idx[2 * t]     = i0;
        d_top_idx[2 * t + 1] = i1;
        d_top_w[2 * t]       = w0;
        d_top_w[2 * t + 1]   = w1;
        atomicAdd(&d_counts[i0], 1);
        atomicAdd(&d_counts[i1], 1);
    }
}

__global__ void scan_kernel() {
    int o = 0;
    for (int e = 0; e < Ee; e++) { d_offsets[e] = o; d_cursor[e] = o; o += d_counts[e]; }
    d_offsets[Ee] = o;
}

__global__ void scatter_kernel() {
    int s = blockIdx.x * blockDim.x + threadIdx.x;
    if (s < T_TOK * TOPK) {
        int e = d_top_idx[s];
        int p = atomicAdd(&d_cursor[e], 1);
        d_perm[p] = s;
    }
}

// ================= GEMM kernels =================

// shared GEMM1: g[:, c0:c0+64] = silu(x@sfc1^T) * (x@sfc2^T)  (dual-B, interleaved rows)
__global__ void __launch_bounds__(256) shared1_mm()
{
    extern __shared__ char smem[];
    int tid = threadIdx.x;
    int row0 = blockIdx.y * 128;
    int c0g  = blockIdx.x * 64;
    int lr = tid >> 1, hb = (tid & 1) * 32;

    const char* aSrc = (const char*)xs16 + (size_t)(row0 + lr) * (Dd * 2) + hb;
    int q = lr >> 3, nn = lr & 7;
    size_t brow = (size_t)(c0g + (q >> 1) * 8 + nn) * (Dd * 2) + hb;
    const char* bSrc = (const char*)((q & 1) ? s2s : s1s) + brow;

    auto epi = [=](float acc[4][4][4], int warpM, int warpN, int lane) {
        int gid = lane >> 2, tig = lane & 3;
        #pragma unroll
        for (int i = 0; i < 4; i++) {
            int m = row0 + warpM * 64 + i * 16 + gid;
            #pragma unroll
            for (int j = 0; j < 2; j++) {
                int col = c0g + (warpN * 2 + j) * 8 + tig * 2;
                size_t idx0 = (size_t)m * (Ss / 2) + (col >> 1);
                g16[idx0] = pack2_single(silu_f(acc[i][2*j][0]) * acc[i][2*j+1][0],
                                         silu_f(acc[i][2*j][1]) * acc[i][2*j+1][1]);
                size_t idx1 = (size_t)(m + 8) * (Ss / 2) + (col >> 1);
                g16[idx1] = pack2_single(silu_f(acc[i][2*j][2]) * acc[i][2*j+1][2],
                                         silu_f(acc[i][2*j][3]) * acc[i][2*j+1][3]);
            }
        }
    };
    gemm_core<Dd / 32>(tid, smem, aSrc, 16, bSrc, epi);
}

// shared GEMM2: out = g @ sfc3^T  (K = S)  -- writes the base value of out
__global__ void __launch_bounds__(256) shared2_mm(float* __restrict__ out)
{
    extern __shared__ char smem[];
    int tid = threadIdx.x;
    int row0 = blockIdx.y * 128;
    int col0 = blockIdx.x * 128;
    int lr = tid >> 1, hb = (tid & 1) * 32;

    const char* aSrc = (const char*)g16 + (size_t)(row0 + lr) * (Ss * 2) + hb;
    const char* bSrc = (const char*)s3s + (size_t)(col0 + lr) * (Ss * 2) + hb;

    auto epi = [=](float acc[4][4][4], int warpM, int warpN, int lane) {
        int gid = lane >> 2, tig = lane & 3;
        #pragma unroll
        for (int i = 0; i < 4; i++) {
            int m = row0 + warpM * 64 + i * 16 + gid;
            #pragma unroll
            for (int t = 0; t < 4; t++) {
                int col = col0 + warpN * 32 + t * 8 + tig * 2;
                *(float2*)(out + (size_t)m * Dd + col)       = make_float2(acc[i][t][0], acc[i][t][1]);
                *(float2*)(out + (size_t)(m + 8) * Dd + col) = make_float2(acc[i][t][2], acc[i][t][3]);
            }
        }
    };
    gemm_core<Ss / 32>(tid, smem, aSrc, 16, bSrc, epi);
}

// MoE GEMM1: h[p] = silu(x[gather] @ w1[e]^T)
__global__ void __launch_bounds__(256) moe1_mm()
{
    int e = blockIdx.z;
    int Ms = d_offsets[e], Me = d_offsets[e + 1];
    int M = Me - Ms;
    int m0 = blockIdx.y * 128;
    if (m0 >= M) return;

    extern __shared__ char smem[];
    int tid = threadIdx.x;
    int col0 = blockIdx.x * 128;
    int lr = tid >> 1, hb = (tid & 1) * 32;

    int mrow = m0 + lr;
    bool okA = (mrow < M);
    int tok = okA ? (d_perm[Ms + mrow] >> 1) : 0;
    const char* aSrc = (const char*)xs16 + (size_t)tok * (Dd * 2) + hb;
    const char* bSrc = (const char*)w1s + ((size_t)e * Hh + col0 + lr) * (Dd * 2) + hb;

    auto epi = [=](float acc[4][4][4], int warpM, int warpN, int lane) {
        int gid = lane >> 2, tig = lane & 3;
        #pragma unroll
        for (int i = 0; i < 4; i++) {
            int mb = m0 + warpM * 64 + i * 16 + gid;
            #pragma unroll
            for (int t = 0; t < 4; t++) {
                int col = col0 + warpN * 32 + t * 8 + tig * 2;
                if (mb < M) {
                    size_t idx = (size_t)(Ms + mb) * (Hh / 2) + (col >> 1);
                    h16[idx] = pack2_single(silu_f(acc[i][t][0]), silu_f(acc[i][t][1]));
                }
                if (mb + 8 < M) {
                    size_t idx = (size_t)(Ms + mb + 8) * (Hh / 2) + (col >> 1);
                    h16[idx] = pack2_single(silu_f(acc[i][t][2]), silu_f(acc[i][t][3]));
                }
            }
        }
    };
    gemm_core<Dd / 32>(tid, smem, aSrc, okA ? 16 : 0, bSrc, epi);
}

// MoE GEMM2: out[token] += wk * (h @ w2[e]^T)   (atomic add onto shared-expert base)
__global__ void __launch_bounds__(256) moe2_mm(float* __restrict__ out)
{
    int e = blockIdx.z;
    int Ms = d_offsets[e], Me = d_offsets[e + 1];
    int M = Me - Ms;
    int m0 = blockIdx.y * 128;
    if (m0 >= M) return;

    extern __shared__ char smem[];
    int tid = threadIdx.x;
    int col0 = blockIdx.x * 128;
    int lr = tid >> 1, hb = (tid & 1) * 32;

    int mrow = m0 + lr;
    bool okA = (mrow < M);
    const char* aSrc = (const char*)h16 + (size_t)(Ms + (okA ? mrow : 0)) * (Hh * 2) + hb;
    const char* bSrc = (const char*)w2s + ((size_t)e * Dd + col0 + lr) * (Hh * 2) + hb;

    auto epi = [=](float acc[4][4][4], int warpM, int warpN, int lane) {
        int gid = lane >> 2, tig = lane & 3;
        #pragma unroll
        for (int i = 0; i < 4; i++) {
            int mb = m0 + warpM * 64 + i * 16 + gid;
            #pragma unroll
            for (int t = 0; t < 4; t++) {
                int col = col0 + warpN * 32 + t * 8 + tig * 2;
                if (mb < M) {
                    int slot = d_perm[Ms + mb];
                    float wk = d_top_w[slot];
                    float* d = out + (size_t)(slot >> 1) * Dd + col;
                    atomicAdd(d,     wk * acc[i][t][0]);
                    atomicAdd(d + 1, wk * acc[i][t][1]);
                }
                if (mb + 8 < M) {
                    int slot = d_perm[Ms + mb + 8];
                    float wk = d_top_w[slot];
                    float* d = out + (size_t)(slot >> 1) * Dd + col;
                    atomicAdd(d,     wk * acc[i][t][2]);
                    atomicAdd(d + 1, wk * acc[i][t][3]);
                }
            }
        }
    };
    gemm_core<Hh / 32>(tid, smem, aSrc, okA ? 16 : 0, bSrc, epi);
}

// ---------------- launch ----------------
extern "C" void kernel_launch(void* const* d_in, const int* in_sizes, int n_in,
                              void* d_out, int out_size)
{
    const float* x     = (const float*)d_in[0];
    const float* gatew = (const float*)d_in[1];
    const float* w1    = (const float*)d_in[2];
    const float* w2    = (const float*)d_in[3];
    const float* sfc1  = (const float*)d_in[4];
    const float* sfc2  = (const float*)d_in[5];
    const float* sfc3  = (const float*)d_in[6];
    float* out = (float*)d_out;

    cudaFuncSetAttribute(shared1_mm, cudaFuncAttributeMaxDynamicSharedMemorySize, SMEM_BYTES);
    cudaFuncSetAttribute(shared2_mm, cudaFuncAttributeMaxDynamicSharedMemorySize, SMEM_BYTES);
    cudaFuncSetAttribute(moe1_mm,    cudaFuncAttributeMaxDynamicSharedMemorySize, SMEM_BYTES);
    cudaFuncSetAttribute(moe2_mm,    cudaFuncAttributeMaxDynamicSharedMemorySize, SMEM_BYTES);

    // fused conversion (+ counts zeroing)
    split_all_kernel<<<(N2_TOT + 255) / 256, 256>>>(x, w1, w2, sfc1, sfc2, sfc3);

    // routing path
    router_kernel<<<T_TOK / 4, 128>>>(x, gatew);
    scan_kernel<<<1, 1>>>();
    scatter_kernel<<<(T_TOK * TOPK + 255) / 256, 256>>>();

    // shared expert
    shared1_mm<<<dim3(Ss / 64, T_TOK / 128), 256, SMEM_BYTES>>>();
    shared2_mm<<<dim3(Dd / 128, T_TOK / 128), 256, SMEM_BYTES>>>(out);

    // sparse MoE (grouped by expert), accumulates into out
    moe1_mm<<<dim3(Hh / 128, (T_TOK * TOPK) / 128, Ee), 256, SMEM_BYTES>>>();
    moe2_mm<<<dim3(Dd / 128, (T_TOK * TOPK) / 128, Ee), 256, SMEM_BYTES>>>(out);
}

// round 16
// speedup vs baseline: 4.9420x; 1.0309x over previous
#include <cuda_runtime.h>
#include <cuda_fp16.h>
#include <math.h>
#include <stdint.h>

// Problem constants
#define T_TOK 4096      // B*L tokens
#define Dd    1024      // model dim
#define Hh    512       // expert hidden
#define Ee    16        // num experts
#define Ss    2048      // shared expert hidden
#define TOPK  2

// ---------------- device scratch (no allocations allowed) ----------------
__device__ uint32_t xs16[(size_t)T_TOK * Dd / 2];
__device__ uint32_t w1s[(size_t)Ee * Hh * Dd / 2];
__device__ uint32_t w2s[(size_t)Ee * Dd * Hh / 2];
__device__ uint32_t s1s[(size_t)Ss * Dd / 2];
__device__ uint32_t s2s[(size_t)Ss * Dd / 2];
__device__ uint32_t s3s[(size_t)Dd * Ss / 2];
__device__ uint32_t g16[(size_t)T_TOK * Ss / 2];
__device__ uint32_t h16[(size_t)T_TOK * TOPK * Hh / 2];
__device__ int   d_top_idx[T_TOK * TOPK];
__device__ float d_top_w[T_TOK * TOPK];
__device__ int   d_offsets[Ee + 1];
__device__ int   d_perm[T_TOK * TOPK];

__device__ __forceinline__ float silu_f(float v) { return v / (1.0f + expf(-v)); }

__device__ __forceinline__ uint32_t smem_u32(const void* p) {
    uint32_t a;
    asm("{ .reg .u64 t; cvta.to.shared.u64 t, %1; cvt.u32.u64 %0, t; }" : "=r"(a) : "l"(p));
    return a;
}
__device__ __forceinline__ uint32_t pack2_single(float a, float b) {
    __half2 h = __floats2half2_rn(a, b);
    return *(uint32_t*)&h;
}

__device__ __forceinline__ void ldsm_x4(uint32_t* r, uint32_t addr) {
    asm volatile("ldmatrix.sync.aligned.m8n8.x4.shared.b16 {%0,%1,%2,%3}, [%4];"
        : "=r"(r[0]), "=r"(r[1]), "=r"(r[2]), "=r"(r[3]) : "r"(addr));
}
__device__ __forceinline__ void ldsm_x2(uint32_t* r, uint32_t addr) {
    asm volatile("ldmatrix.sync.aligned.m8n8.x2.shared.b16 {%0,%1}, [%2];"
        : "=r"(r[0]), "=r"(r[1]) : "r"(addr));
}
__device__ __forceinline__ void mma16816(float* c, const uint32_t* a, const uint32_t* b) {
    asm volatile(
        "mma.sync.aligned.m16n8k16.row.col.f32.f16.f16.f32 "
        "{%0,%1,%2,%3}, {%4,%5,%6,%7}, {%8,%9}, {%0,%1,%2,%3};"
        : "+f"(c[0]), "+f"(c[1]), "+f"(c[2]), "+f"(c[3])
        : "r"(a[0]), "r"(a[1]), "r"(a[2]), "r"(a[3]), "r"(b[0]), "r"(b[1]));
}

__device__ __forceinline__ void cp16(uint32_t dst, const void* src, int sz) {
    asm volatile("cp.async.cg.shared.global [%0], [%1], 16, %2;"
                 :: "r"(dst), "l"(src), "r"(sz) : "memory");
}
#define CP_COMMIT() asm volatile("cp.async.commit_group;" ::: "memory")
#define CP_WAIT0()  asm volatile("cp.async.wait_group 0;" ::: "memory")
#define CP_WAIT1()  asm volatile("cp.async.wait_group 1;" ::: "memory")

// SMEM per stage: A@0, B@10240 (128 rows x 80B each). 3 stages, stride 20480.
#define STAGE_BYTES 20480
#define SMEM_BYTES  61440

// ====== GEMM core: 128x128 tile, 8 warps (2x4), 64x32 warp tile, cp.async x3 ======
template <int NC, typename FE>
__device__ __forceinline__ void gemm_core(
    int tid, char* smem,
    const char* aSrc, int szA,
    const char* bSrc, FE epi)
{
    const int lane  = tid & 31;
    const int wid   = tid >> 5;
    const int warpM = wid >> 2;
    const int warpN = wid & 3;
    uint32_t sb = smem_u32(smem);
    const int lr = tid >> 1;
    uint32_t dstBase = sb + (uint32_t)(lr * 80 + (tid & 1) * 32);

    float acc[4][4][4];
    #pragma unroll
    for (int i = 0; i < 4; i++)
        #pragma unroll
        for (int t = 0; t < 4; t++)
            #pragma unroll
            for (int r = 0; r < 4; r++) acc[i][t][r] = 0.f;

    auto issue = [&](int c) {
        uint32_t d = dstBase + (uint32_t)(c % 3) * (uint32_t)STAGE_BYTES;
        const char* pA = aSrc + (size_t)c * 64;
        const char* pB = bSrc + (size_t)c * 64;
        cp16(d,          pA,      szA); cp16(d + 16,         pA + 16, szA);
        cp16(d + 10240,  pB,      16);  cp16(d + 10240 + 16, pB + 16, 16);
    };

    issue(0); CP_COMMIT();
    if (NC > 1) { issue(1); CP_COMMIT(); }

    const uint32_t arow  = (uint32_t)((warpM * 64 + (lane & 15)) * 80);
    const uint32_t brow  = (uint32_t)((warpN * 32 + (lane & 7)) * 80);
    const uint32_t akoff = (uint32_t)(((lane >> 4) & 1) * 16);
    const uint32_t bkoff = (uint32_t)(((lane >> 3) & 1) * 16);

    #pragma unroll 1
    for (int c = 0; c < NC; c++) {
        if (c + 1 < NC) CP_WAIT1(); else CP_WAIT0();
        __syncthreads();
        uint32_t bufb = sb + (uint32_t)(c % 3) * (uint32_t)STAGE_BYTES;
        #pragma unroll
        for (int s = 0; s < 2; s++) {
            uint32_t ak = bufb + arow + (uint32_t)(s * 32) + akoff;
            uint32_t bk = bufb + 10240u + brow + (uint32_t)(s * 32) + bkoff;
            uint32_t af[4][4], bf[4][2];
            #pragma unroll
            for (int i = 0; i < 4; i++)
                ldsm_x4(af[i], ak + (uint32_t)(i * 16 * 80));
            #pragma unroll
            for (int t = 0; t < 4; t++)
                ldsm_x2(bf[t], bk + (uint32_t)(t * 8 * 80));
            #pragma unroll
            for (int i = 0; i < 4; i++)
                #pragma unroll
                for (int t = 0; t < 4; t++) mma16816(acc[i][t], af[i], bf[t]);
        }
        if (c + 2 < NC) { issue(c + 2); CP_COMMIT(); }
    }
    epi(acc, warpM, warpN, lane);
}

// ---------------- fused prologue: router + out-zero + operand split ----------------
#define N2_X   (T_TOK * Dd / 2)
#define N2_W1  (Ee * Hh * Dd / 2)
#define N2_W2  (Ee * Dd * Hh / 2)
#define N2_S1  (Ss * Dd / 2)
#define N2_S2  (Ss * Dd / 2)
#define N2_S3  (Dd * Ss / 2)
#define N2_TOT (N2_X + N2_W1 + N2_W2 + N2_S1 + N2_S2 + N2_S3)

#define NB_ROUTER (T_TOK / 8)                 // 512 blocks, 8 warps = 8 tokens each
#define NB_ZERO   ((T_TOK * Dd / 4) / 256)    // 4096 blocks, float4 zero of out
#define NB_SPLIT  ((N2_TOT + 255) / 256)      // 53248 blocks
#define NB_PRE    (NB_ROUTER + NB_ZERO + NB_SPLIT)

__global__ void __launch_bounds__(256) pre_kernel(
    const float* __restrict__ x,  const float* __restrict__ gw,
    const float* __restrict__ w1, const float* __restrict__ w2,
    const float* __restrict__ sfc1, const float* __restrict__ sfc2,
    const float* __restrict__ sfc3, float* __restrict__ out)
{
    int b = blockIdx.x;
    int tid = threadIdx.x;
    if (b < NB_ROUTER) {
        // ---- router: one warp per token, x registers-resident ----
        int warp = tid >> 5;
        int lane = tid & 31;
        int t = b * 8 + warp;
        const float* xr = x + (size_t)t * Dd;
        float xv[32];
        #pragma unroll
        for (int j = 0; j < 32; j++) xv[j] = xr[lane + 32 * j];
        float logits[Ee];
        #pragma unroll 1
        for (int e = 0; e < Ee; e++) {
            const float* w = gw + (size_t)e * Dd;
            float p = 0.0f;
            #pragma unroll
            for (int j = 0; j < 32; j++) p += xv[j] * w[lane + 32 * j];
            #pragma unroll
            for (int o = 16; o; o >>= 1) p += __shfl_down_sync(0xffffffffu, p, o);
            if (lane == 0) logits[e] = p;
        }
        if (lane == 0) {
            int i0 = 0; float v0 = logits[0];
            #pragma unroll
            for (int e = 1; e < Ee; e++) if (logits[e] > v0) { v0 = logits[e]; i0 = e; }
            int i1 = -1; float v1 = -3.0e38f;
            #pragma unroll
            for (int e = 0; e < Ee; e++) if (e != i0 && logits[e] > v1) { v1 = logits[e]; i1 = e; }
            float ex = expf(v1 - v0);
            d_top_idx[2 * t]     = i0;
            d_top_idx[2 * t + 1] = i1;
            d_top_w[2 * t]       = 1.0f / (1.0f + ex);
            d_top_w[2 * t + 1]   = ex / (1.0f + ex);
        }
        return;
    }
    b -= NB_ROUTER;
    if (b < NB_ZERO) {
        // ---- zero out (moe2/shared2 accumulate atomically) ----
        int i = b * 256 + tid;
        ((float4*)out)[i] = make_float4(0.f, 0.f, 0.f, 0.f);
        return;
    }
    b -= NB_ZERO;
    // ---- fp32 -> fp16 operand conversion ----
    int i = b * 256 + tid;
    if (i >= N2_TOT) return;
    const float* src;
    uint32_t* dst;
    int j = i;
    if (j < N2_X)                     { src = x;    dst = xs16; }
    else if ((j -= N2_X)  < N2_W1)    { src = w1;   dst = w1s; }
    else if ((j -= N2_W1) < N2_W2)    { src = w2;   dst = w2s; }
    else if ((j -= N2_W2) < N2_S1)    { src = sfc1; dst = s1s; }
    else if ((j -= N2_S1) < N2_S2)    { src = sfc2; dst = s2s; }
    else       { j -= N2_S2;            src = sfc3; dst = s3s; }
    float2 v = ((const float2*)src)[j];
    dst[j] = pack2_single(v.x, v.y);
}

// ---------------- scan + scatter (single block) ----------------
__global__ void scan_scatter_kernel()
{
    __shared__ int cnt[Ee];
    __shared__ int off[Ee];
    int tid = threadIdx.x;
    if (tid < Ee) cnt[tid] = 0;
    __syncthreads();
    for (int s = tid; s < T_TOK * TOPK; s += blockDim.x)
        atomicAdd(&cnt[d_top_idx[s]], 1);
    __syncthreads();
    if (tid == 0) {
        int o = 0;
        for (int e = 0; e < Ee; e++) { off[e] = o; d_offsets[e] = o; o += cnt[e]; }
        d_offsets[Ee] = o;
    }
    __syncthreads();
    if (tid < Ee) cnt[tid] = off[tid];   // reuse as cursors
    __syncthreads();
    for (int s = tid; s < T_TOK * TOPK; s += blockDim.x) {
        int e = d_top_idx[s];
        int p = atomicAdd(&cnt[e], 1);
        d_perm[p] = s;
    }
}

// ================= merged GEMM kernels =================

// kernel A: blocks [0,1024) = shared GEMM1 ; blocks [1024, 1024+4096) = MoE GEMM1
#define A_S1_BLOCKS 1024
#define A_MOE_BLOCKS (4 * 64 * Ee)
__global__ void __launch_bounds__(256) gemmA_mm()
{
    extern __shared__ char smem[];
    int b = blockIdx.x;
    int tid = threadIdx.x;
    int lr = tid >> 1, hb = (tid & 1) * 32;

    if (b < A_S1_BLOCKS) {
        // ---- shared GEMM1: g = silu(x@sfc1^T) * (x@sfc2^T), dual-B interleaved ----
        int c0g  = (b & 31) * 64;
        int row0 = (b >> 5) * 128;
        const char* aSrc = (const char*)xs16 + (size_t)(row0 + lr) * (Dd * 2) + hb;
        int q = lr >> 3, nn = lr & 7;
        size_t brow = (size_t)(c0g + (q >> 1) * 8 + nn) * (Dd * 2) + hb;
        const char* bSrc = (const char*)((q & 1) ? s2s : s1s) + brow;

        auto epi = [=](float acc[4][4][4], int warpM, int warpN, int lane) {
            int gid = lane >> 2, tig = lane & 3;
            #pragma unroll
            for (int i = 0; i < 4; i++) {
                int m = row0 + warpM * 64 + i * 16 + gid;
                #pragma unroll
                for (int j = 0; j < 2; j++) {
                    int col = c0g + (warpN * 2 + j) * 8 + tig * 2;
                    size_t idx0 = (size_t)m * (Ss / 2) + (col >> 1);
                    g16[idx0] = pack2_single(silu_f(acc[i][2*j][0]) * acc[i][2*j+1][0],
                                             silu_f(acc[i][2*j][1]) * acc[i][2*j+1][1]);
                    size_t idx1 = (size_t)(m + 8) * (Ss / 2) + (col >> 1);
                    g16[idx1] = pack2_single(silu_f(acc[i][2*j][2]) * acc[i][2*j+1][2],
                                             silu_f(acc[i][2*j][3]) * acc[i][2*j+1][3]);
                }
            }
        };
        gemm_core<Dd / 32>(tid, smem, aSrc, 16, bSrc, epi);
    } else {
        // ---- MoE GEMM1: h = silu(x[gather] @ w1[e]^T) ----
        int b2 = b - A_S1_BLOCKS;
        int col0 = (b2 & 3) * 128;
        int rest = b2 >> 2;
        int m0 = (rest & 63) * 128;
        int e = rest >> 6;
        int Ms = d_offsets[e], Me = d_offsets[e + 1];
        int M = Me - Ms;
        if (m0 >= M) return;

        int mrow = m0 + lr;
        bool okA = (mrow < M);
        int tok = okA ? (d_perm[Ms + mrow] >> 1) : 0;
        const char* aSrc = (const char*)xs16 + (size_t)tok * (Dd * 2) + hb;
        const char* bSrc = (const char*)w1s + ((size_t)e * Hh + col0 + lr) * (Dd * 2) + hb;

        auto epi = [=](float acc[4][4][4], int warpM, int warpN, int lane) {
            int gid = lane >> 2, tig = lane & 3;
            #pragma unroll
            for (int i = 0; i < 4; i++) {
                int mb = m0 + warpM * 64 + i * 16 + gid;
                #pragma unroll
                for (int t = 0; t < 4; t++) {
                    int col = col0 + warpN * 32 + t * 8 + tig * 2;
                    if (mb < M) {
                        size_t idx = (size_t)(Ms + mb) * (Hh / 2) + (col >> 1);
                        h16[idx] = pack2_single(silu_f(acc[i][t][0]), silu_f(acc[i][t][1]));
                    }
                    if (mb + 8 < M) {
                        size_t idx = (size_t)(Ms + mb + 8) * (Hh / 2) + (col >> 1);
                        h16[idx] = pack2_single(silu_f(acc[i][t][2]), silu_f(acc[i][t][3]));
                    }
                }
            }
        };
        gemm_core<Dd / 32>(tid, smem, aSrc, okA ? 16 : 0, bSrc, epi);
    }
}

// kernel B: blocks [0,256) = shared GEMM2 (atomic) ; blocks [256, 256+8192) = MoE GEMM2 (atomic)
#define B_S2_BLOCKS 256
#define B_MOE_BLOCKS (8 * 64 * Ee)
__global__ void __launch_bounds__(256) gemmB_mm(float* __restrict__ out)
{
    extern __shared__ char smem[];
    int b = blockIdx.x;
    int tid = threadIdx.x;
    int lr = tid >> 1, hb = (tid & 1) * 32;

    if (b < B_S2_BLOCKS) {
        // ---- shared GEMM2: out += g @ sfc3^T ----
        int col0 = (b & 7) * 128;
        int row0 = (b >> 3) * 128;
        const char* aSrc = (const char*)g16 + (size_t)(row0 + lr) * (Ss * 2) + hb;
        const char* bSrc = (const char*)s3s + (size_t)(col0 + lr) * (Ss * 2) + hb;

        auto epi = [=](float acc[4][4][4], int warpM, int warpN, int lane) {
            int gid = lane >> 2, tig = lane & 3;
            #pragma unroll
            for (int i = 0; i < 4; i++) {
                int m = row0 + warpM * 64 + i * 16 + gid;
                #pragma unroll
                for (int t = 0; t < 4; t++) {
                    int col = col0 + warpN * 32 + t * 8 + tig * 2;
                    float* d0 = out + (size_t)m * Dd + col;
                    float* d1 = out + (size_t)(m + 8) * Dd + col;
                    atomicAdd(d0,     acc[i][t][0]);
                    atomicAdd(d0 + 1, acc[i][t][1]);
                    atomicAdd(d1,     acc[i][t][2]);
                    atomicAdd(d1 + 1, acc[i][t][3]);
                }
            }
        };
        gemm_core<Ss / 32>(tid, smem, aSrc, 16, bSrc, epi);
    } else {
        // ---- MoE GEMM2: out[token] += wk * (h @ w2[e]^T) ----
        int b2 = b - B_S2_BLOCKS;
        int col0 = (b2 & 7) * 128;
        int rest = b2 >> 3;
        int m0 = (rest & 63) * 128;
        int e = rest >> 6;
        int Ms = d_offsets[e], Me = d_offsets[e + 1];
        int M = Me - Ms;
        if (m0 >= M) return;

        int mrow = m0 + lr;
        bool okA = (mrow < M);
        const char* aSrc = (const char*)h16 + (size_t)(Ms + (okA ? mrow : 0)) * (Hh * 2) + hb;
        const char* bSrc = (const char*)w2s + ((size_t)e * Dd + col0 + lr) * (Hh * 2) + hb;

        auto epi = [=](float acc[4][4][4], int warpM, int warpN, int lane) {
            int gid = lane >> 2, tig = lane & 3;
            #pragma unroll
            for (int i = 0; i < 4; i++) {
                int mb = m0 + warpM * 64 + i * 16 + gid;
                #pragma unroll
                for (int t = 0; t < 4; t++) {
                    int col = col0 + warpN * 32 + t * 8 + tig * 2;
                    if (mb < M) {
                        int slot = d_perm[Ms + mb];
                        float wk = d_top_w[slot];
                        float* d = out + (size_t)(slot >> 1) * Dd + col;
                        atomicAdd(d,     wk * acc[i][t][0]);
                        atomicAdd(d + 1, wk * acc[i][t][1]);
                    }
                    if (mb + 8 < M) {
                        int slot = d_perm[Ms + mb + 8];
                        float wk = d_top_w[slot];
                        float* d = out + (size_t)(slot >> 1) * Dd + col;
                        atomicAdd(d,     wk * acc[i][t][2]);
                        atomicAdd(d + 1, wk * acc[i][t][3]);
                    }
                }
            }
        };
        gemm_core<Hh / 32>(tid, smem, aSrc, okA ? 16 : 0, bSrc, epi);
    }
}

// ---------------- launch ----------------
extern "C" void kernel_launch(void* const* d_in, const int* in_sizes, int n_in,
                              void* d_out, int out_size)
{
    const float* x     = (const float*)d_in[0];
    const float* gatew = (const float*)d_in[1];
    const float* w1    = (const float*)d_in[2];
    const float* w2    = (const float*)d_in[3];
    const float* sfc1  = (const float*)d_in[4];
    const float* sfc2  = (const float*)d_in[5];
    const float* sfc3  = (const float*)d_in[6];
    float* out = (float*)d_out;

    cudaFuncSetAttribute(gemmA_mm, cudaFuncAttributeMaxDynamicSharedMemorySize, SMEM_BYTES);
    cudaFuncSetAttribute(gemmB_mm, cudaFuncAttributeMaxDynamicSharedMemorySize, SMEM_BYTES);

    // 1) fused prologue: router + out-zero + fp16 operand conversion
    pre_kernel<<<NB_PRE, 256>>>(x, gatew, w1, w2, sfc1, sfc2, sfc3, out);

    // 2) expert grouping
    scan_scatter_kernel<<<1, 512>>>();

    // 3) shared GEMM1 + MoE GEMM1 (merged)
    gemmA_mm<<<A_S1_BLOCKS + A_MOE_BLOCKS, 256, SMEM_BYTES>>>();

    // 4) shared GEMM2 + MoE GEMM2 (merged, atomic accumulate into out)
    gemmB_mm<<<B_S2_BLOCKS + B_MOE_BLOCKS, 256, SMEM_BYTES>>>(out);
}